// round 14
// baseline (speedup 1.0000x reference)
#include <cuda_runtime.h>
#include <math.h>
#include <stdint.h>

#define Bq   128
#define Sq   256
#define DMq  128
#define Hq   8
#define DKq  16
#define NTOPq 30
#define SKq  30
#define KSq  7
#define KKq  (Sq*KSq)   // 1792

// ---------------- scratch (device globals; no allocations allowed) -------------
__device__ float g_qrot [Bq*Sq*DMq];
__device__ float g_krot [Bq*Sq*DMq];
__device__ float g_kconv[Bq*Sq*DMq];
__device__ float g_vconv[Bq*Sq*DMq];
__device__ float g_mean [Bq*DMq];
__device__ float g_ot   [Bq*Hq*NTOPq*DKq];
__device__ float g_cos  [Sq*64];
__device__ float g_sin  [Sq*64];
__device__ int   g_mtop [Bq*Hq*NTOPq];

// A fragments (bf16 hi/lo), fragment-ordered: slice (z,tile,it): 512 uint4
#define ATILE_U4 512
__device__ uint4 g_Ahi[2*2*56*ATILE_U4];
__device__ uint4 g_Alo[2*2*56*ATILE_U4];
// B fragments per (z,b,chunk): 1024 uint4 = 16KB, exact smem image.
__device__ uint4 g_Bfrag[(size_t)2*Bq*56*1024];

// ---------------- trig table ----------------------------------------------------
__global__ void trig_kernel() {
    int idx = blockIdx.x * blockDim.x + threadIdx.x;
    if (idx >= Sq * 64) return;
    int s = idx >> 6, i = idx & 63;
    double p  = pow(10000.0, (double)(2 * i) / 128.0);
    float  pf = (float)p;
    float  freq = 1.0f / pf;
    float  ang  = (float)s * freq;
    g_cos[idx] = (float)cos((double)ang);
    g_sin[idx] = (float)sin((double)ang);
}

// ---------------- rotary --------------------------------------------------------
__global__ void rotary_kernel(const float* __restrict__ q, const float* __restrict__ k) {
    int idx = blockIdx.x * blockDim.x + threadIdx.x;
    if (idx >= Bq * Sq * 32) return;
    int i4 = idx & 31;
    int bs = idx >> 5;
    int s  = bs & (Sq - 1);
    const float2* c2 = reinterpret_cast<const float2*>(g_cos + s * 64 + 2 * i4);
    const float2* s2 = reinterpret_cast<const float2*>(g_sin + s * 64 + 2 * i4);
    float2 cc = *c2, ss = *s2;
    size_t base = (size_t)bs * DMq + 4 * i4;
    float4 qv = *reinterpret_cast<const float4*>(q + base);
    float4 kv = *reinterpret_cast<const float4*>(k + base);
    float4 qo, ko;
    qo.x = qv.x * cc.x - qv.y * ss.x;  qo.y = qv.x * ss.x + qv.y * cc.x;
    qo.z = qv.z * cc.y - qv.w * ss.y;  qo.w = qv.z * ss.y + qv.w * cc.y;
    ko.x = kv.x * cc.x - kv.y * ss.x;  ko.y = kv.x * ss.x + kv.y * cc.x;
    ko.z = kv.z * cc.y - kv.w * ss.y;  ko.w = kv.z * ss.y + kv.w * cc.y;
    *reinterpret_cast<float4*>(g_qrot + base) = qo;
    *reinterpret_cast<float4*>(g_krot + base) = ko;
}

// ---------------- bf16 split helpers --------------------------------------------
__device__ __forceinline__ void split_pack(float ve, float vo, uint32_t& h, uint32_t& l) {
    asm("cvt.rn.bf16x2.f32 %0, %1, %2;" : "=r"(h) : "f"(vo), "f"(ve));
    float fe = __uint_as_float(h << 16);
    float fo = __uint_as_float(h & 0xFFFF0000u);
    float le = ve - fe, lo = vo - fo;
    asm("cvt.rn.bf16x2.f32 %0, %1, %2;" : "=r"(l) : "f"(lo), "f"(le));
}
__device__ __forceinline__ void mma_bf16(float* d, const uint32_t* a,
                                         uint32_t b0, uint32_t b1) {
    asm("mma.sync.aligned.m16n8k16.row.col.f32.bf16.bf16.f32 "
        "{%0,%1,%2,%3}, {%4,%5,%6,%7}, {%8,%9}, {%0,%1,%2,%3};"
        : "+f"(d[0]), "+f"(d[1]), "+f"(d[2]), "+f"(d[3])
        : "r"(a[0]), "r"(a[1]), "r"(a[2]), "r"(a[3]), "r"(b0), "r"(b1));
}

#define CP_ASYNC16(dst_u32, src_ptr) \
    asm volatile("cp.async.cg.shared.global [%0], [%1], 16;" :: "r"(dst_u32), "l"(src_ptr))
#define CP_ASYNC16_CA(dst_u32, src_ptr) \
    asm volatile("cp.async.ca.shared.global [%0], [%1], 16;" :: "r"(dst_u32), "l"(src_ptr))
#define CP_COMMIT()  asm volatile("cp.async.commit_group;")
#define CP_WAIT0()   asm volatile("cp.async.wait_group 0;")

__device__ __forceinline__ uint32_t smem_u32(const void* p) {
    uint32_t a;
    asm("{ .reg .u64 t; cvta.to.shared.u64 t, %1; cvt.u32.u64 %0, t; }" : "=r"(a) : "l"(p));
    return a;
}

// ---------------- w -> bf16 hi/lo A fragments (once per launch) ------------------
__global__ void wprep_kernel(const float* __restrict__ wk, const float* __restrict__ wv) {
    int i = blockIdx.x * 256 + threadIdx.x;
    if (i >= 2 * 2 * 56 * ATILE_U4) return;
    int lane = i & 31;
    int i2 = i >> 5;
    int m  = i2 & 7;
    int i3 = i2 >> 3;
    int s  = i3 & 1;
    int i4 = i3 >> 1;
    int it = i4 % 56;
    int i5 = i4 / 56;
    int tile = i5 & 1;
    int z    = i5 >> 1;

    const float* w = (z == 0) ? wk : wv;
    int r  = lane >> 2, c = lane & 3;
    int so = tile * 128 + m * 16 + r;
    int k0 = it * 32 + s * 16 + 2 * c;

    const float* r0p = w + (size_t)so * KKq;
    const float* r8p = w + (size_t)(so + 8) * KKq;

    uint32_t h0, l0, h1, l1, h2, l2, h3, l3;
    split_pack(r0p[k0],     r0p[k0 + 1], h0, l0);
    split_pack(r8p[k0],     r8p[k0 + 1], h1, l1);
    split_pack(r0p[k0 + 8], r0p[k0 + 9], h2, l2);
    split_pack(r8p[k0 + 8], r8p[k0 + 9], h3, l3);
    g_Ahi[i] = make_uint4(h0, h1, h2, h3);
    g_Alo[i] = make_uint4(l0, l1, l2, l3);
}

// ---------------- x -> bf16 hi/lo B fragments (smem row-staged) ------------------
// Window: pad cols 2..7 zero, row data at cols 8..135 (16B-aligned float4 stores).
// value x[si, d+t-6] = xs[(si-si0)*136 + d + t + 2].
__global__ void bprep_kernel(const float* __restrict__ vin) {
    __shared__ __align__(16) float xs[6 * 136];
    int it = blockIdx.x, b = blockIdx.y, z = blockIdx.z;
    const float* __restrict__ xb = ((z == 0) ? (const float*)g_krot : vin)
                                   + (size_t)b * Sq * DMq;
    uint4* dst = g_Bfrag + ((size_t)(z * Bq + b) * 56 + it) * 1024;
    int tid = threadIdx.x;
    int si0 = (32 * it) / 7;

    if (tid < 36) {
        int r = tid / 6, c = 2 + (tid - (tid / 6) * 6);
        xs[r * 136 + c] = 0.f;
    }
    if (tid < 192) {
        int r = tid >> 5, q = tid & 31;
        int gr = si0 + r;
        if (gr < Sq)
            *reinterpret_cast<float4*>(&xs[r * 136 + 8 + 4 * q]) =
                *reinterpret_cast<const float4*>(xb + (size_t)gr * DMq + 4 * q);
    }
    __syncthreads();

#pragma unroll
    for (int r = 0; r < 4; r++) {
        int e = tid + 256 * r;
        int s    = e >> 9;
        int pn   = (e >> 5) & 15;
        int lane = e & 31;
        int dd = lane >> 2, cS = lane & 3;
        int d  = 8 * pn + dd;
        uint32_t w[4];
#pragma unroll
        for (int whi = 0; whi < 2; whi++) {
            int cp  = s * 8 + whi * 4 + cS;
            int kkA = 32 * it + 2 * cp;
            int siA = kkA / 7, tA = kkA - 7 * siA;
            int kkB = kkA + 1;
            int siB = kkB / 7, tB = kkB - 7 * siB;
            float ve = xs[(siA - si0) * 136 + d + tA + 2];
            float vo = xs[(siB - si0) * 136 + d + tB + 2];
            uint32_t h, l;
            split_pack(ve, vo, h, l);
            if (s == 0) { w[whi] = h; w[2 + whi] = l; }
            else        { w[2 + whi] = h; w[whi] = l; }
        }
        dst[e] = make_uint4(w[0], w[1], w[2], w[3]);
    }
}

// ================= conv: bare cp.async + LDS + MMA mainloop =====================
// grid (b, so_t, z): consecutive CTAs share (so_t,z) -> co-resident CTAs read the
// SAME A chunks; A copied with cp.async.ca so the 2nd CTA hits L1.
#define SA_BUF_B 16384
#define SB_OFF   (2 * SA_BUF_B)            // 32768
#define SB_BUF_B 16384
#define CONV_SMEM5 (SB_OFF + 2 * SB_BUF_B) // 65536

__global__ void __launch_bounds__(256, 2)
conv_mma_kernel(const float* __restrict__ bk, const float* __restrict__ bv) {
    extern __shared__ __align__(16) char smem[];

    const int b    = blockIdx.x;
    const int so_t = blockIdx.y;
    const int z    = blockIdx.z;
    const int tid  = threadIdx.x;
    const int lane = tid & 31;
    const int wid  = tid >> 5;
    const int wm   = wid & 3;
    const int wn   = wid >> 2;

    float* __restrict__ yb = ((z == 0) ? g_kconv : g_vconv) + (size_t)b * Sq * DMq;
    const float* __restrict__ bias = (z == 0) ? bk : bv;

    const uint4* gAh = g_Ahi + (size_t)((z * 2 + so_t) * 56) * ATILE_U4;
    const uint4* gAl = g_Alo + (size_t)((z * 2 + so_t) * 56) * ATILE_U4;
    const uint4* gB  = g_Bfrag + ((size_t)(z * Bq + b) * 56) * 1024;

    const uint32_t sbase = smem_u32(smem);

    float acc[2][8][4];
#pragma unroll
    for (int i = 0; i < 2; i++)
#pragma unroll
        for (int j = 0; j < 8; j++)
#pragma unroll
            for (int q = 0; q < 4; q++) acc[i][j][q] = 0.f;

    // ---- prologue: A[0] hi/lo (L1-cached) + B[0] into buffer 0 ----
    {
#pragma unroll
        for (int r = 0; r < 2; r++) {
            int i = tid + 256 * r;
            CP_ASYNC16_CA(sbase + i * 16,        gAh + i);
            CP_ASYNC16_CA(sbase + 8192 + i * 16, gAl + i);
        }
#pragma unroll
        for (int r = 0; r < 4; r++) {
            int i = tid + 256 * r;
            CP_ASYNC16(sbase + SB_OFF + i * 16, gB + i);
        }
        CP_COMMIT();
    }

#pragma unroll 1
    for (int it = 0; it < 56; it++) {
        const int cur = it & 1;

        CP_WAIT0();        // A[it], B[it] landed
        __syncthreads();   // visible to all; prior MMA reads of cur^1 done

        // ---- issue next copies A[it+1], B[it+1] into cur^1 ----
        if (it < 55) {
            const uint4* sH = gAh + (size_t)(it + 1) * ATILE_U4;
            const uint4* sL = gAl + (size_t)(it + 1) * ATILE_U4;
            const uint4* sB = gB  + (size_t)(it + 1) * 1024;
            uint32_t dstA = sbase + (cur ^ 1) * SA_BUF_B;
            uint32_t dstB = sbase + SB_OFF + (cur ^ 1) * SB_BUF_B;
#pragma unroll
            for (int r = 0; r < 2; r++) {
                int i = tid + 256 * r;
                CP_ASYNC16_CA(dstA + i * 16,        sH + i);
                CP_ASYNC16_CA(dstA + 8192 + i * 16, sL + i);
            }
#pragma unroll
            for (int r = 0; r < 4; r++) {
                int i = tid + 256 * r;
                CP_ASYNC16(dstB + i * 16, sB + i);
            }
            CP_COMMIT();
        }

        // ---- MMA phase on A[cur], B[cur] ----
        const char* abase = smem + cur * SA_BUF_B;
        const char* bbase = smem + SB_OFF + cur * SB_BUF_B;
#pragma unroll
        for (int s = 0; s < 2; s++) {
            uint4 AH[2], AL[2];
#pragma unroll
            for (int mt = 0; mt < 2; mt++) {
                int fi = ((s * 8 + wm * 2 + mt) * 32 + lane) * 16;
                AH[mt] = *(const uint4*)(abase + fi);
                AL[mt] = *(const uint4*)(abase + 8192 + fi);
            }
#pragma unroll
            for (int pp = 0; pp < 4; pp++) {
                const int p0 = 2 * pp, p1 = 2 * pp + 1;
                const uint4 F0 = *(const uint4*)(
                    bbase + ((s * 16 + wn * 8 + p0) * 32 + lane) * 16);
                const uint4 F1 = *(const uint4*)(
                    bbase + ((s * 16 + wn * 8 + p1) * 32 + lane) * 16);
                const uint32_t F0h0 = s ? F0.z : F0.x, F0h1 = s ? F0.w : F0.y;
                const uint32_t F0l0 = s ? F0.x : F0.z, F0l1 = s ? F0.y : F0.w;
                const uint32_t F1h0 = s ? F1.z : F1.x, F1h1 = s ? F1.w : F1.y;
                const uint32_t F1l0 = s ? F1.x : F1.z, F1l1 = s ? F1.y : F1.w;
                mma_bf16(acc[0][p0], (const uint32_t*)&AH[0], F0h0, F0h1);
                mma_bf16(acc[1][p0], (const uint32_t*)&AH[1], F0h0, F0h1);
                mma_bf16(acc[0][p1], (const uint32_t*)&AH[0], F1h0, F1h1);
                mma_bf16(acc[1][p1], (const uint32_t*)&AH[1], F1h0, F1h1);
                mma_bf16(acc[0][p0], (const uint32_t*)&AH[0], F0l0, F0l1);
                mma_bf16(acc[1][p0], (const uint32_t*)&AH[1], F0l0, F0l1);
                mma_bf16(acc[0][p1], (const uint32_t*)&AH[0], F1l0, F1l1);
                mma_bf16(acc[1][p1], (const uint32_t*)&AH[1], F1l0, F1l1);
                mma_bf16(acc[0][p0], (const uint32_t*)&AL[0], F0h0, F0h1);
                mma_bf16(acc[1][p0], (const uint32_t*)&AL[1], F0h0, F0h1);
                mma_bf16(acc[0][p1], (const uint32_t*)&AL[0], F1h0, F1h1);
                mma_bf16(acc[1][p1], (const uint32_t*)&AL[1], F1h0, F1h1);
            }
        }
    }

    // ---- epilogue ----
    const int rbase = so_t * 128 + wm * 32 + (lane >> 2);
    const int cb    = wn * 64 + (lane & 3) * 2;
#pragma unroll
    for (int mt = 0; mt < 2; mt++) {
        int row = rbase + mt * 16;
        float bA = bias[row], bB = bias[row + 8];
#pragma unroll
        for (int p = 0; p < 8; p++) {
            int col = cb + p * 8;
            float2 v0 = make_float2(acc[mt][p][0] + bA, acc[mt][p][1] + bA);
            float2 v1 = make_float2(acc[mt][p][2] + bB, acc[mt][p][3] + bB);
            *reinterpret_cast<float2*>(&yb[(size_t)row * DMq + col])       = v0;
            *reinterpret_cast<float2*>(&yb[(size_t)(row + 8) * DMq + col]) = v1;
        }
    }
}

// ---------------- per-(b,d) mean of vconv ---------------------------------------
__global__ void mean_kernel() {
    __shared__ float psum[8][DMq];
    int b  = blockIdx.x;
    int ty = threadIdx.x >> 5, q = threadIdx.x & 31;
    const float* vb = g_vconv + (size_t)b * Sq * DMq;
    float4 acc = make_float4(0.f, 0.f, 0.f, 0.f);
#pragma unroll 4
    for (int k = 0; k < 32; k++) {
        float4 v = *reinterpret_cast<const float4*>(vb + (size_t)(ty + 8 * k) * DMq + 4 * q);
        acc.x += v.x; acc.y += v.y; acc.z += v.z; acc.w += v.w;
    }
    *reinterpret_cast<float4*>(&psum[ty][4 * q]) = acc;
    __syncthreads();
    if (threadIdx.x < DMq) {
        float s = 0.f;
#pragma unroll
        for (int j = 0; j < 8; j++) s += psum[j][threadIdx.x];
        g_mean[b * DMq + threadIdx.x] = s * (1.0f / 256.0f);
    }
}

// ======= fused sampled-QK + top-30 selection + attention (one block per bh) =====
#define FK_KS   0
#define FK_VS   20480
#define FK_SI   40960
#define FK_MS   71680
#define FK_MT   72704
#define FK_SMEM 72832

__global__ void __launch_bounds__(256)
select_attend_kernel(const int* __restrict__ idxs) {
    extern __shared__ __align__(16) char fsm[];
    float* ksh  = (float*)(fsm + FK_KS);
    float* vsh  = (float*)(fsm + FK_VS);
    int*   sidx = (int*)(fsm + FK_SI);
    float* Msh  = (float*)(fsm + FK_MS);
    int*   smtop= (int*)(fsm + FK_MT);

    int bh = blockIdx.x;
    int b  = bh >> 3, h = bh & 7;
    int tid = threadIdx.x;
    int l   = tid;

#pragma unroll
    for (int rep = 0; rep < 4; rep++) {
        int i = tid + 256 * rep;
        int row = i >> 2, c = i & 3;
        size_t g = ((size_t)b * Sq + row) * DMq + h * DKq + 4 * c;
        *reinterpret_cast<float4*>(&ksh[row * 20 + 4 * c]) =
            *reinterpret_cast<const float4*>(&g_kconv[g]);
        *reinterpret_cast<float4*>(&vsh[row * 20 + 4 * c]) =
            *reinterpret_cast<const float4*>(&g_vconv[g]);
    }
    for (int i = tid; i < (Sq * SKq) / 4; i += 256)
        reinterpret_cast<int4*>(sidx)[i] = reinterpret_cast<const int4*>(idxs)[i];
    __syncthreads();

    // ---- M[l] = max - mean of sampled QK ----
    {
        const float4* qp = reinterpret_cast<const float4*>(
            g_qrot + ((size_t)b * Sq + l) * DMq + h * DKq);
        float4 q0 = qp[0], q1 = qp[1], q2 = qp[2], q3 = qp[3];

        float mx = -3.402823466e38f;
        float sum = 0.f;
#pragma unroll 1
        for (int s = 0; s < SKq; s++) {
            int j = sidx[l * SKq + s];
            const float4* kp = reinterpret_cast<const float4*>(&ksh[j * 20]);
            float4 k0 = kp[0], k1 = kp[1], k2 = kp[2], k3 = kp[3];
            float dot = 0.f;
            dot += q0.x * k0.x; dot += q0.y * k0.y; dot += q0.z * k0.z; dot += q0.w * k0.w;
            dot += q1.x * k1.x; dot += q1.y * k1.y; dot += q1.z * k1.z; dot += q1.w * k1.w;
            dot += q2.x * k2.x; dot += q2.y * k2.y; dot += q2.z * k2.z; dot += q2.w * k2.w;
            dot += q3.x * k3.x; dot += q3.y * k3.y; dot += q3.z * k3.z; dot += q3.w * k3.w;
            mx = fmaxf(mx, dot);
            sum += dot;
        }
        Msh[l] = mx - sum * (1.0f / 30.0f);
    }
    __syncthreads();

    if (l < 32) {
        float mv[8];
#pragma unroll
        for (int j = 0; j < 8; j++) mv[j] = Msh[l + 32 * j];
#pragma unroll 1
        for (int u = 0; u < NTOPq; u++) {
            float bvv = mv[0];
            int   bj  = 0;
#pragma unroll
            for (int j = 1; j < 8; j++)
                if (mv[j] > bvv) { bvv = mv[j]; bj = j; }
            int bidx = l + 32 * bj;
#pragma unroll
            for (int off = 16; off > 0; off >>= 1) {
                float ov = __shfl_xor_sync(0xffffffffu, bvv, off);
                int   oi = __shfl_xor_sync(0xffffffffu, bidx, off);
                if (ov > bvv || (ov == bvv && oi < bidx)) { bvv = ov; bidx = oi; }
            }
            if (l == 0) { g_mtop[bh * NTOPq + u] = bidx; smtop[u] = bidx; }
            if ((bidx & 31) == l) {
                int slot = bidx >> 5;
#pragma unroll
                for (int j = 0; j < 8; j++)
                    if (j == slot) mv[j] = -3.402823466e38f;
            }
        }
    }
    __syncthreads();

    const int warp = tid >> 5;
    const int lane = tid & 31;

#pragma unroll 1
    for (int jj = 0; jj < 4; jj++) {
        int u = warp + 8 * jj;
        if (u >= NTOPq) break;
        int lsel = smtop[u];
        float qv = g_qrot[((size_t)b * Sq + lsel) * DMq + h * DKq + (lane & 15)];
        float qq[16];
#pragma unroll
        for (int i = 0; i < 16; i++) qq[i] = __shfl_sync(0xffffffffu, qv, i);

        float dot[8];
#pragma unroll
        for (int m = 0; m < 8; m++) {
            const float4* kr = reinterpret_cast<const float4*>(&ksh[(lane + 32 * m) * 20]);
            float4 k0 = kr[0], k1 = kr[1], k2 = kr[2], k3 = kr[3];
            float dd = 0.f;
            dd += qq[0]  * k0.x; dd += qq[1]  * k0.y; dd += qq[2]  * k0.z; dd += qq[3]  * k0.w;
            dd += qq[4]  * k1.x; dd += qq[5]  * k1.y; dd += qq[6]  * k1.z; dd += qq[7]  * k1.w;
            dd += qq[8]  * k2.x; dd += qq[9]  * k2.y; dd += qq[10] * k2.z; dd += qq[11] * k2.w;
            dd += qq[12] * k3.x; dd += qq[13] * k3.y; dd += qq[14] * k3.z; dd += qq[15] * k3.w;
            dot[m] = dd;
        }
        float mx = -3.402823466e38f;
#pragma unroll
        for (int m = 0; m < 8; m++) { dot[m] *= 0.25f; mx = fmaxf(mx, dot[m]); }
#pragma unroll
        for (int off = 16; off > 0; off >>= 1)
            mx = fmaxf(mx, __shfl_xor_sync(0xffffffffu, mx, off));
        float p[8];
        float sum = 0.f;
#pragma unroll
        for (int m = 0; m < 8; m++) { p[m] = expf(dot[m] - mx); sum += p[m]; }
#pragma unroll
        for (int off = 16; off > 0; off >>= 1)
            sum += __shfl_xor_sync(0xffffffffu, sum, off);

        float o[16];
#pragma unroll
        for (int d = 0; d < 16; d++) o[d] = 0.f;
#pragma unroll
        for (int m = 0; m < 8; m++) {
            float pm = p[m];
            const float4* vr = reinterpret_cast<const float4*>(&vsh[(lane + 32 * m) * 20]);
#pragma unroll
            for (int c = 0; c < 4; c++) {
                float4 vv = vr[c];
                o[4*c]   += pm * vv.x;
                o[4*c+1] += pm * vv.y;
                o[4*c+2] += pm * vv.z;
                o[4*c+3] += pm * vv.w;
            }
        }
#pragma unroll
        for (int off = 16; off > 0; off >>= 1)
#pragma unroll
            for (int d = 0; d < 16; d++)
                o[d] += __shfl_xor_sync(0xffffffffu, o[d], off);

        if (lane == 0) {
            float inv = 1.0f / sum;
            float* op = g_ot + ((size_t)bh * NTOPq + u) * DKq;
#pragma unroll
            for (int d4 = 0; d4 < 4; d4++) {
                float4 v = make_float4(o[4*d4]*inv, o[4*d4+1]*inv, o[4*d4+2]*inv, o[4*d4+3]*inv);
                *reinterpret_cast<float4*>(op + 4 * d4) = v;
            }
        }
    }
}

// ---------------- base output: out[b,s,:] = mean(b) @ W^T + bias ------------------
__global__ void base_kernel(const float* __restrict__ w, const float* __restrict__ bias,
                            float* __restrict__ out) {
    __shared__ float meansh[DMq];
    __shared__ float baseo[DMq];
    int b = blockIdx.x;
    int tid = threadIdx.x;
    if (tid < DMq) meansh[tid] = g_mean[b * DMq + tid];
    __syncthreads();
    if (tid < DMq) {
        const float4* wr = reinterpret_cast<const float4*>(w + (size_t)tid * DMq);
        float dot = 0.f;
#pragma unroll
        for (int q = 0; q < 32; q++) {
            float4 wv = wr[q];
            dot += wv.x * meansh[4*q] + wv.y * meansh[4*q+1]
                 + wv.z * meansh[4*q+2] + wv.w * meansh[4*q+3];
        }
        baseo[tid] = dot + bias[tid];
    }
    __syncthreads();
    const float4* b4 = reinterpret_cast<const float4*>(baseo);
    float4* o4 = reinterpret_cast<float4*>(out + (size_t)b * Sq * DMq);
#pragma unroll 4
    for (int k = 0; k < 32; k++) {
        int idx = tid + 256 * k;
        int s = idx >> 5, q = idx & 31;
        o4[s * 32 + q] = b4[q];
    }
}

// ---------------- scatter corrections: out[b,s,:] += (ot - mean_h) @ Wh^T --------
__global__ void scatter_kernel(const float* __restrict__ w, float* __restrict__ out) {
    int bh = blockIdx.x;
    int b  = bh >> 3, h = bh & 7;
    int j  = threadIdx.x;
    int lane = j & 31;

    float wh[16];
    const float4* wr = reinterpret_cast<const float4*>(w + (size_t)j * DMq + h * DKq);
#pragma unroll
    for (int q = 0; q < 4; q++) {
        float4 v = wr[q];
        wh[4*q] = v.x; wh[4*q+1] = v.y; wh[4*q+2] = v.z; wh[4*q+3] = v.w;
    }
    float msl = (lane < 16) ? g_mean[b * DMq + h * DKq + lane] : 0.f;
    float mi[16];
#pragma unroll
    for (int i = 0; i < 16; i++) mi[i] = __shfl_sync(0xffffffffu, msl, i);

#pragma unroll 1
    for (int u = 0; u < NTOPq; u++) {
        int s = g_mtop[bh * NTOPq + u];
        float otv = (lane < 16) ? g_ot[((size_t)bh * NTOPq + u) * DKq + lane] : 0.f;
        float corr = 0.f;
#pragma unroll
        for (int i = 0; i < 16; i++)
            corr += (__shfl_sync(0xffffffffu, otv, i) - mi[i]) * wh[i];
        atomicAdd(&out[((size_t)b * Sq + s) * DMq + j], corr);
    }
}

// -------------------------------------------------------------------------------
extern "C" void kernel_launch(void* const* d_in, const int* in_sizes, int n_in,
                              void* d_out, int out_size) {
    const float* query = (const float*)d_in[0];
    const float* key   = (const float*)d_in[1];
    const float* value = (const float*)d_in[2];
    const float* ckw   = (const float*)d_in[3];
    const float* ckb   = (const float*)d_in[4];
    const float* cvw   = (const float*)d_in[5];
    const float* cvb   = (const float*)d_in[6];
    const float* lw    = (const float*)d_in[7];
    const float* lb    = (const float*)d_in[8];
    const int*   isamp = (const int*)d_in[9];
    float* out = (float*)d_out;

    static int attr_set = 0;
    if (!attr_set) {
        cudaFuncSetAttribute(conv_mma_kernel, cudaFuncAttributeMaxDynamicSharedMemorySize,
                             CONV_SMEM5);
        cudaFuncSetAttribute(select_attend_kernel, cudaFuncAttributeMaxDynamicSharedMemorySize,
                             FK_SMEM);
        attr_set = 1;
    }

    trig_kernel<<<(Sq * 64 + 255) / 256, 256>>>();
    rotary_kernel<<<(Bq * Sq * 32 + 255) / 256, 256>>>(query, key);
    wprep_kernel<<<(2 * 2 * 56 * ATILE_U4 + 255) / 256, 256>>>(ckw, cvw);

    dim3 bpg(56, Bq, 2);
    bprep_kernel<<<bpg, 256>>>(value);

    dim3 cgrid(Bq, 2, 2);
    conv_mma_kernel<<<cgrid, 256, CONV_SMEM5>>>(ckb, cvb);

    mean_kernel<<<Bq, 256>>>();
    select_attend_kernel<<<Bq * Hq, 256, FK_SMEM>>>(isamp);

    base_kernel<<<Bq, 256>>>(lw, lb, out);
    scatter_kernel<<<Bq * Hq, 128>>>(lw, out);
}

// round 15
// speedup vs baseline: 1.5972x; 1.5972x over previous
#include <cuda_runtime.h>
#include <math.h>
#include <stdint.h>

#define Bq   128
#define Sq   256
#define DMq  128
#define Hq   8
#define DKq  16
#define NTOPq 30
#define SKq  30
#define KSq  7
#define KKq  (Sq*KSq)   // 1792

// ---------------- scratch (device globals; no allocations allowed) -------------
__device__ float g_qrot [Bq*Sq*DMq];
__device__ float g_krot [Bq*Sq*DMq];
__device__ float g_kconv[Bq*Sq*DMq];
__device__ float g_vconv[Bq*Sq*DMq];
__device__ float g_mean [Bq*DMq];
__device__ float g_ot   [Bq*Hq*NTOPq*DKq];
__device__ float g_cos  [Sq*64];
__device__ float g_sin  [Sq*64];
__device__ int   g_mtop [Bq*Hq*NTOPq];

// A fragments (bf16 hi/lo), fragment-ordered: slice (z,tile,it): 512 uint4
#define ATILE_U4 512
__device__ uint4 g_Ahi[2*2*56*ATILE_U4];
__device__ uint4 g_Alo[2*2*56*ATILE_U4];

// ---------------- trig table (exact double, tiny cost) --------------------------
__global__ void trig_kernel() {
    int idx = blockIdx.x * blockDim.x + threadIdx.x;
    if (idx >= Sq * 64) return;
    int s = idx >> 6, i = idx & 63;
    double p  = pow(10000.0, (double)(2 * i) / 128.0);
    float  pf = (float)p;
    float  freq = 1.0f / pf;
    float  ang  = (float)s * freq;
    g_cos[idx] = (float)cos((double)ang);
    g_sin[idx] = (float)sin((double)ang);
}

// ---------------- rotary on q and k (float4 = 2 pairs per thread) ---------------
__global__ void rotary_kernel(const float* __restrict__ q, const float* __restrict__ k) {
    int idx = blockIdx.x * blockDim.x + threadIdx.x;
    if (idx >= Bq * Sq * 32) return;
    int i4 = idx & 31;
    int bs = idx >> 5;
    int s  = bs & (Sq - 1);
    const float2* c2 = reinterpret_cast<const float2*>(g_cos + s * 64 + 2 * i4);
    const float2* s2 = reinterpret_cast<const float2*>(g_sin + s * 64 + 2 * i4);
    float2 cc = *c2, ss = *s2;
    size_t base = (size_t)bs * DMq + 4 * i4;
    float4 qv = *reinterpret_cast<const float4*>(q + base);
    float4 kv = *reinterpret_cast<const float4*>(k + base);
    float4 qo, ko;
    qo.x = qv.x * cc.x - qv.y * ss.x;  qo.y = qv.x * ss.x + qv.y * cc.x;
    qo.z = qv.z * cc.y - qv.w * ss.y;  qo.w = qv.z * ss.y + qv.w * cc.y;
    ko.x = kv.x * cc.x - kv.y * ss.x;  ko.y = kv.x * ss.x + kv.y * cc.x;
    ko.z = kv.z * cc.y - kv.w * ss.y;  ko.w = kv.z * ss.y + kv.w * cc.y;
    *reinterpret_cast<float4*>(g_qrot + base) = qo;
    *reinterpret_cast<float4*>(g_krot + base) = ko;
}

// ---------------- bf16 split helpers --------------------------------------------
__device__ __forceinline__ void split_pack(float ve, float vo, uint32_t& h, uint32_t& l) {
    asm("cvt.rn.bf16x2.f32 %0, %1, %2;" : "=r"(h) : "f"(vo), "f"(ve));
    float fe = __uint_as_float(h << 16);
    float fo = __uint_as_float(h & 0xFFFF0000u);
    float le = ve - fe, lo = vo - fo;
    asm("cvt.rn.bf16x2.f32 %0, %1, %2;" : "=r"(l) : "f"(lo), "f"(le));
}
__device__ __forceinline__ void mma_bf16(float* d, const uint32_t* a,
                                         uint32_t b0, uint32_t b1) {
    asm volatile(
        "mma.sync.aligned.m16n8k16.row.col.f32.bf16.bf16.f32 "
        "{%0,%1,%2,%3}, {%4,%5,%6,%7}, {%8,%9}, {%0,%1,%2,%3};"
        : "+f"(d[0]), "+f"(d[1]), "+f"(d[2]), "+f"(d[3])
        : "r"(a[0]), "r"(a[1]), "r"(a[2]), "r"(a[3]), "r"(b0), "r"(b1));
}

#define CP_ASYNC16(dst_u32, src_ptr) \
    asm volatile("cp.async.cg.shared.global [%0], [%1], 16;" :: "r"(dst_u32), "l"(src_ptr))
#define CP_COMMIT()  asm volatile("cp.async.commit_group;")
#define CP_WAIT0()   asm volatile("cp.async.wait_group 0;")

__device__ __forceinline__ uint32_t smem_u32(const void* p) {
    uint32_t a;
    asm("{ .reg .u64 t; cvta.to.shared.u64 t, %1; cvt.u32.u64 %0, t; }" : "=r"(a) : "l"(p));
    return a;
}

// ---------------- w -> bf16 hi/lo fragments (run once per launch) ----------------
__global__ void wprep_kernel(const float* __restrict__ wk, const float* __restrict__ wv) {
    int i = blockIdx.x * 256 + threadIdx.x;
    if (i >= 2 * 2 * 56 * ATILE_U4) return;
    int lane = i & 31;
    int i2 = i >> 5;
    int m  = i2 & 7;
    int i3 = i2 >> 3;
    int s  = i3 & 1;
    int i4 = i3 >> 1;
    int it = i4 % 56;
    int i5 = i4 / 56;
    int tile = i5 & 1;
    int z    = i5 >> 1;

    const float* w = (z == 0) ? wk : wv;
    int r  = lane >> 2, c = lane & 3;
    int so = tile * 128 + m * 16 + r;
    int k0 = it * 32 + s * 16 + 2 * c;

    const float* r0p = w + (size_t)so * KKq;
    const float* r8p = w + (size_t)(so + 8) * KKq;

    uint32_t h0, l0, h1, l1, h2, l2, h3, l3;
    split_pack(r0p[k0],     r0p[k0 + 1], h0, l0);
    split_pack(r8p[k0],     r8p[k0 + 1], h1, l1);
    split_pack(r0p[k0 + 8], r0p[k0 + 9], h2, l2);
    split_pack(r8p[k0 + 8], r8p[k0 + 9], h3, l3);
    g_Ahi[i] = make_uint4(h0, h1, h2, h3);
    g_Alo[i] = make_uint4(l0, l1, l2, l3);
}

// ================= conv as mma.sync bf16 GEMM (3-split) =========================
// Round-8 proven config: A via cp.async.cg from fragment store; B staged in-kernel
// from a cp.async'd x-row window (xw); two barriers per chunk.
#define SA_BUF_B 16384
#define SB_OFF   (2 * SA_BUF_B)            // 32768
#define SB_BUF_B 16384
#define XW_OFF   (SB_OFF + 2 * SB_BUF_B)   // 65536
#define XW_BUF_B (6 * 136 * 4)             // 3264
#define CONV_SMEM3 (XW_OFF + 2 * XW_BUF_B) // 72064

__global__ void __launch_bounds__(256, 2)
conv_mma_kernel(const float* __restrict__ vin,
                const float* __restrict__ bk, const float* __restrict__ bv) {
    extern __shared__ __align__(16) char smem[];

    const int so_t = blockIdx.x;
    const int b    = blockIdx.y;
    const int z    = blockIdx.z;
    const int tid  = threadIdx.x;
    const int lane = tid & 31;
    const int wid  = tid >> 5;
    const int wm   = wid & 3;
    const int wn   = wid >> 2;

    const float* __restrict__ xb = ((z == 0) ? (const float*)g_krot : vin)
                                   + (size_t)b * Sq * DMq;
    float* __restrict__ yb       = ((z == 0) ? g_kconv : g_vconv) + (size_t)b * Sq * DMq;
    const float* __restrict__ bias = (z == 0) ? bk : bv;

    const uint4* gAh = g_Ahi + (size_t)((z * 2 + so_t) * 56) * ATILE_U4;
    const uint4* gAl = g_Alo + (size_t)((z * 2 + so_t) * 56) * ATILE_U4;

    const uint32_t sbase = smem_u32(smem);

    // ---- B staging role constants ----
    const int cp   = tid & 15;
    const int drow = tid >> 4;
    const int sS   = cp >> 3;
    const int cS   = cp & 3;
    const int whi  = (cp >> 2) & 1;
    const int laneF = ((drow & 7) << 2) | cS;
    const int pn0   = drow >> 3;
    const int wbh = (sS ? 8 : 0) + whi * 4;
    const int wbl = (sS ? 0 : 8) + whi * 4;
    const uint32_t b_thr_off = (uint32_t)(SB_OFF + ((sS * 16 + pn0) * 32 + laneF) * 16);

    // zero the permanent pad cols (2..7) of xw, both buffers
    if (tid < 72) {
        int p  = tid / 36;
        int rm = tid - p * 36;
        int r  = rm / 6;
        int c  = 2 + (rm - r * 6);
        *(float*)(smem + XW_OFF + p * XW_BUF_B + (r * 136 + c) * 4) = 0.f;
    }

    float acc[2][8][4];
#pragma unroll
    for (int i = 0; i < 2; i++)
#pragma unroll
        for (int j = 0; j < 8; j++)
#pragma unroll
            for (int q = 0; q < 4; q++) acc[i][j][q] = 0.f;

    // ---- prologue: cp.async A chunk 0 + xw rows for chunk 0 ----
    {
#pragma unroll
        for (int r = 0; r < 2; r++) {
            int i = tid + 256 * r;
            CP_ASYNC16(sbase + i * 16,        gAh + i);
            CP_ASYNC16(sbase + 8192 + i * 16, gAl + i);
        }
        if (tid < 192) {
            int r = tid >> 5, q = tid & 31;
            uint32_t dst = sbase + XW_OFF + (uint32_t)((r * 136 + 8 + 4 * q) * 4);
            CP_ASYNC16(dst, xb + (size_t)r * DMq + 4 * q);
        }
        CP_COMMIT();
    }

#pragma unroll 1
    for (int it = 0; it < 56; it++) {
        const int cur = it & 1;

        CP_WAIT0();
        __syncthreads();

        // ---- stage B[cur] from xw[cur] ----
        {
            const float* xwb = (const float*)(smem + XW_OFF + cur * XW_BUF_B);
            int base = 32 * it;
            int si0  = base / 7;
            int kkA  = base + 2 * cp;
            int siA  = kkA / 7, tA = kkA - 7 * siA;
            int kkB  = kkA + 1;
            int siB  = kkB / 7, tB = kkB - 7 * siB;
            const float* peB = xwb + (siA - si0) * 136 + tA + 2 + drow;
            const float* poB = xwb + (siB - si0) * 136 + tB + 2 + drow;
            char* bdst = smem + b_thr_off + cur * SB_BUF_B;
#pragma unroll
            for (int j = 0; j < 8; j++) {
                uint32_t h, l;
                split_pack(peB[16 * j], poB[16 * j], h, l);
                *(uint32_t*)(bdst + j * 1024 + wbh) = h;
                *(uint32_t*)(bdst + j * 1024 + wbl) = l;
            }
        }

        // ---- issue next chunk's copies (A + xw) ----
        if (it < 55) {
            const uint4* sH = gAh + (size_t)(it + 1) * ATILE_U4;
            const uint4* sL = gAl + (size_t)(it + 1) * ATILE_U4;
            uint32_t dstA = sbase + (cur ^ 1) * SA_BUF_B;
#pragma unroll
            for (int r = 0; r < 2; r++) {
                int i = tid + 256 * r;
                CP_ASYNC16(dstA + i * 16,        sH + i);
                CP_ASYNC16(dstA + 8192 + i * 16, sL + i);
            }
            int si0n = (32 * (it + 1)) / 7;
            if (tid < 192) {
                int r = tid >> 5, q = tid & 31;
                int gr = si0n + r;
                if (gr < Sq) {
                    uint32_t dst = sbase + XW_OFF + (cur ^ 1) * XW_BUF_B
                                 + (uint32_t)((r * 136 + 8 + 4 * q) * 4);
                    CP_ASYNC16(dst, xb + (size_t)gr * DMq + 4 * q);
                }
            }
            CP_COMMIT();
        }
        __syncthreads();

        // ---- MMA phase ----
        const char* abase = smem + cur * SA_BUF_B;
        const char* bbase = smem + SB_OFF + cur * SB_BUF_B;
#pragma unroll
        for (int s = 0; s < 2; s++) {
            uint4 AH[2], AL[2];
#pragma unroll
            for (int mt = 0; mt < 2; mt++) {
                int fi = ((s * 8 + wm * 2 + mt) * 32 + lane) * 16;
                AH[mt] = *(const uint4*)(abase + fi);
                AL[mt] = *(const uint4*)(abase + 8192 + fi);
            }
#pragma unroll
            for (int p = 0; p < 8; p++) {
                const uint4 F = *(const uint4*)(
                    bbase + ((s * 16 + wn * 8 + p) * 32 + lane) * 16);
                const uint32_t bh0 = s ? F.z : F.x;
                const uint32_t bh1 = s ? F.w : F.y;
                const uint32_t bl0 = s ? F.x : F.z;
                const uint32_t bl1 = s ? F.y : F.w;
                mma_bf16(acc[0][p], (const uint32_t*)&AH[0], bh0, bh1);
                mma_bf16(acc[1][p], (const uint32_t*)&AH[1], bh0, bh1);
                mma_bf16(acc[0][p], (const uint32_t*)&AH[0], bl0, bl1);
                mma_bf16(acc[1][p], (const uint32_t*)&AH[1], bl0, bl1);
                mma_bf16(acc[0][p], (const uint32_t*)&AL[0], bh0, bh1);
                mma_bf16(acc[1][p], (const uint32_t*)&AL[1], bh0, bh1);
            }
        }
    }

    // ---- epilogue ----
    const int rbase = so_t * 128 + wm * 32 + (lane >> 2);
    const int cb    = wn * 64 + (lane & 3) * 2;
#pragma unroll
    for (int mt = 0; mt < 2; mt++) {
        int row = rbase + mt * 16;
        float bA = bias[row], bB = bias[row + 8];
#pragma unroll
        for (int p = 0; p < 8; p++) {
            int col = cb + p * 8;
            float2 v0 = make_float2(acc[mt][p][0] + bA, acc[mt][p][1] + bA);
            float2 v1 = make_float2(acc[mt][p][2] + bB, acc[mt][p][3] + bB);
            *reinterpret_cast<float2*>(&yb[(size_t)row * DMq + col])       = v0;
            *reinterpret_cast<float2*>(&yb[(size_t)(row + 8) * DMq + col]) = v1;
        }
    }
}

// ---------------- per-(b,d) mean of vconv ---------------------------------------
__global__ void mean_kernel() {
    __shared__ float psum[8][DMq];
    int b  = blockIdx.x;
    int ty = threadIdx.x >> 5, q = threadIdx.x & 31;
    const float* vb = g_vconv + (size_t)b * Sq * DMq;
    float4 acc = make_float4(0.f, 0.f, 0.f, 0.f);
#pragma unroll 4
    for (int k = 0; k < 32; k++) {
        float4 v = *reinterpret_cast<const float4*>(vb + (size_t)(ty + 8 * k) * DMq + 4 * q);
        acc.x += v.x; acc.y += v.y; acc.z += v.z; acc.w += v.w;
    }
    *reinterpret_cast<float4*>(&psum[ty][4 * q]) = acc;
    __syncthreads();
    if (threadIdx.x < DMq) {
        float s = 0.f;
#pragma unroll
        for (int j = 0; j < 8; j++) s += psum[j][threadIdx.x];
        g_mean[b * DMq + threadIdx.x] = s * (1.0f / 256.0f);
    }
}

// ======= fused sampled-QK + top-30 selection + attention (one block per bh) =====
#define FK_KS   0
#define FK_VS   20480
#define FK_SI   40960
#define FK_MS   71680
#define FK_MT   72704
#define FK_SMEM 72832

__global__ void __launch_bounds__(256)
select_attend_kernel(const int* __restrict__ idxs) {
    extern __shared__ __align__(16) char fsm[];
    float* ksh  = (float*)(fsm + FK_KS);
    float* vsh  = (float*)(fsm + FK_VS);
    int*   sidx = (int*)(fsm + FK_SI);
    float* Msh  = (float*)(fsm + FK_MS);
    int*   smtop= (int*)(fsm + FK_MT);

    int bh = blockIdx.x;
    int b  = bh >> 3, h = bh & 7;
    int tid = threadIdx.x;
    int l   = tid;

#pragma unroll
    for (int rep = 0; rep < 4; rep++) {
        int i = tid + 256 * rep;
        int row = i >> 2, c = i & 3;
        size_t g = ((size_t)b * Sq + row) * DMq + h * DKq + 4 * c;
        *reinterpret_cast<float4*>(&ksh[row * 20 + 4 * c]) =
            *reinterpret_cast<const float4*>(&g_kconv[g]);
        *reinterpret_cast<float4*>(&vsh[row * 20 + 4 * c]) =
            *reinterpret_cast<const float4*>(&g_vconv[g]);
    }
    for (int i = tid; i < (Sq * SKq) / 4; i += 256)
        reinterpret_cast<int4*>(sidx)[i] = reinterpret_cast<const int4*>(idxs)[i];
    __syncthreads();

    // ---- M[l] = max - mean of sampled QK ----
    {
        const float4* qp = reinterpret_cast<const float4*>(
            g_qrot + ((size_t)b * Sq + l) * DMq + h * DKq);
        float4 q0 = qp[0], q1 = qp[1], q2 = qp[2], q3 = qp[3];

        float mx = -3.402823466e38f;
        float sum = 0.f;
#pragma unroll 1
        for (int s = 0; s < SKq; s++) {
            int j = sidx[l * SKq + s];
            const float4* kp = reinterpret_cast<const float4*>(&ksh[j * 20]);
            float4 k0 = kp[0], k1 = kp[1], k2 = kp[2], k3 = kp[3];
            float dot = 0.f;
            dot += q0.x * k0.x; dot += q0.y * k0.y; dot += q0.z * k0.z; dot += q0.w * k0.w;
            dot += q1.x * k1.x; dot += q1.y * k1.y; dot += q1.z * k1.z; dot += q1.w * k1.w;
            dot += q2.x * k2.x; dot += q2.y * k2.y; dot += q2.z * k2.z; dot += q2.w * k2.w;
            dot += q3.x * k3.x; dot += q3.y * k3.y; dot += q3.z * k3.z; dot += q3.w * k3.w;
            mx = fmaxf(mx, dot);
            sum += dot;
        }
        Msh[l] = mx - sum * (1.0f / 30.0f);
    }
    __syncthreads();

    if (l < 32) {
        float mv[8];
#pragma unroll
        for (int j = 0; j < 8; j++) mv[j] = Msh[l + 32 * j];
#pragma unroll 1
        for (int u = 0; u < NTOPq; u++) {
            float bvv = mv[0];
            int   bj  = 0;
#pragma unroll
            for (int j = 1; j < 8; j++)
                if (mv[j] > bvv) { bvv = mv[j]; bj = j; }
            int bidx = l + 32 * bj;
#pragma unroll
            for (int off = 16; off > 0; off >>= 1) {
                float ov = __shfl_xor_sync(0xffffffffu, bvv, off);
                int   oi = __shfl_xor_sync(0xffffffffu, bidx, off);
                if (ov > bvv || (ov == bvv && oi < bidx)) { bvv = ov; bidx = oi; }
            }
            if (l == 0) { g_mtop[bh * NTOPq + u] = bidx; smtop[u] = bidx; }
            if ((bidx & 31) == l) {
                int slot = bidx >> 5;
#pragma unroll
                for (int j = 0; j < 8; j++)
                    if (j == slot) mv[j] = -3.402823466e38f;
            }
        }
    }
    __syncthreads();

    const int warp = tid >> 5;
    const int lane = tid & 31;

#pragma unroll 1
    for (int jj = 0; jj < 4; jj++) {
        int u = warp + 8 * jj;
        if (u >= NTOPq) break;
        int lsel = smtop[u];
        float qv = g_qrot[((size_t)b * Sq + lsel) * DMq + h * DKq + (lane & 15)];
        float qq[16];
#pragma unroll
        for (int i = 0; i < 16; i++) qq[i] = __shfl_sync(0xffffffffu, qv, i);

        float dot[8];
#pragma unroll
        for (int m = 0; m < 8; m++) {
            const float4* kr = reinterpret_cast<const float4*>(&ksh[(lane + 32 * m) * 20]);
            float4 k0 = kr[0], k1 = kr[1], k2 = kr[2], k3 = kr[3];
            float dd = 0.f;
            dd += qq[0]  * k0.x; dd += qq[1]  * k0.y; dd += qq[2]  * k0.z; dd += qq[3]  * k0.w;
            dd += qq[4]  * k1.x; dd += qq[5]  * k1.y; dd += qq[6]  * k1.z; dd += qq[7]  * k1.w;
            dd += qq[8]  * k2.x; dd += qq[9]  * k2.y; dd += qq[10] * k2.z; dd += qq[11] * k2.w;
            dd += qq[12] * k3.x; dd += qq[13] * k3.y; dd += qq[14] * k3.z; dd += qq[15] * k3.w;
            dot[m] = dd;
        }
        float mx = -3.402823466e38f;
#pragma unroll
        for (int m = 0; m < 8; m++) { dot[m] *= 0.25f; mx = fmaxf(mx, dot[m]); }
#pragma unroll
        for (int off = 16; off > 0; off >>= 1)
            mx = fmaxf(mx, __shfl_xor_sync(0xffffffffu, mx, off));
        float p[8];
        float sum = 0.f;
#pragma unroll
        for (int m = 0; m < 8; m++) { p[m] = expf(dot[m] - mx); sum += p[m]; }
#pragma unroll
        for (int off = 16; off > 0; off >>= 1)
            sum += __shfl_xor_sync(0xffffffffu, sum, off);

        float o[16];
#pragma unroll
        for (int d = 0; d < 16; d++) o[d] = 0.f;
#pragma unroll
        for (int m = 0; m < 8; m++) {
            float pm = p[m];
            const float4* vr = reinterpret_cast<const float4*>(&vsh[(lane + 32 * m) * 20]);
#pragma unroll
            for (int c = 0; c < 4; c++) {
                float4 vv = vr[c];
                o[4*c]   += pm * vv.x;
                o[4*c+1] += pm * vv.y;
                o[4*c+2] += pm * vv.z;
                o[4*c+3] += pm * vv.w;
            }
        }
#pragma unroll
        for (int off = 16; off > 0; off >>= 1)
#pragma unroll
            for (int d = 0; d < 16; d++)
                o[d] += __shfl_xor_sync(0xffffffffu, o[d], off);

        if (lane == 0) {
            float inv = 1.0f / sum;
            float* op = g_ot + ((size_t)bh * NTOPq + u) * DKq;
#pragma unroll
            for (int d4 = 0; d4 < 4; d4++) {
                float4 v = make_float4(o[4*d4]*inv, o[4*d4+1]*inv, o[4*d4+2]*inv, o[4*d4+3]*inv);
                *reinterpret_cast<float4*>(op + 4 * d4) = v;
            }
        }
    }
}

// ---------------- base output: out[b,s,:] = mean(b) @ W^T + bias ------------------
__global__ void base_kernel(const float* __restrict__ w, const float* __restrict__ bias,
                            float* __restrict__ out) {
    __shared__ float meansh[DMq];
    __shared__ float baseo[DMq];
    int b = blockIdx.x;
    int tid = threadIdx.x;
    if (tid < DMq) meansh[tid] = g_mean[b * DMq + tid];
    __syncthreads();
    if (tid < DMq) {
        const float4* wr = reinterpret_cast<const float4*>(w + (size_t)tid * DMq);
        float dot = 0.f;
#pragma unroll
        for (int q = 0; q < 32; q++) {
            float4 wv = wr[q];
            dot += wv.x * meansh[4*q] + wv.y * meansh[4*q+1]
                 + wv.z * meansh[4*q+2] + wv.w * meansh[4*q+3];
        }
        baseo[tid] = dot + bias[tid];
    }
    __syncthreads();
    const float4* b4 = reinterpret_cast<const float4*>(baseo);
    float4* o4 = reinterpret_cast<float4*>(out + (size_t)b * Sq * DMq);
#pragma unroll 4
    for (int k = 0; k < 32; k++) {
        int idx = tid + 256 * k;
        int s = idx >> 5, q = idx & 31;
        o4[s * 32 + q] = b4[q];
    }
}

// ---------------- scatter corrections: out[b,s,:] += (ot - mean_h) @ Wh^T --------
__global__ void scatter_kernel(const float* __restrict__ w, float* __restrict__ out) {
    int bh = blockIdx.x;
    int b  = bh >> 3, h = bh & 7;
    int j  = threadIdx.x;
    int lane = j & 31;

    float wh[16];
    const float4* wr = reinterpret_cast<const float4*>(w + (size_t)j * DMq + h * DKq);
#pragma unroll
    for (int q = 0; q < 4; q++) {
        float4 v = wr[q];
        wh[4*q] = v.x; wh[4*q+1] = v.y; wh[4*q+2] = v.z; wh[4*q+3] = v.w;
    }
    float msl = (lane < 16) ? g_mean[b * DMq + h * DKq + lane] : 0.f;
    float mi[16];
#pragma unroll
    for (int i = 0; i < 16; i++) mi[i] = __shfl_sync(0xffffffffu, msl, i);

#pragma unroll 1
    for (int u = 0; u < NTOPq; u++) {
        int s = g_mtop[bh * NTOPq + u];
        float otv = (lane < 16) ? g_ot[((size_t)bh * NTOPq + u) * DKq + lane] : 0.f;
        float corr = 0.f;
#pragma unroll
        for (int i = 0; i < 16; i++)
            corr += (__shfl_sync(0xffffffffu, otv, i) - mi[i]) * wh[i];
        atomicAdd(&out[((size_t)b * Sq + s) * DMq + j], corr);
    }
}

// -------------------------------------------------------------------------------
extern "C" void kernel_launch(void* const* d_in, const int* in_sizes, int n_in,
                              void* d_out, int out_size) {
    const float* query = (const float*)d_in[0];
    const float* key   = (const float*)d_in[1];
    const float* value = (const float*)d_in[2];
    const float* ckw   = (const float*)d_in[3];
    const float* ckb   = (const float*)d_in[4];
    const float* cvw   = (const float*)d_in[5];
    const float* cvb   = (const float*)d_in[6];
    const float* lw    = (const float*)d_in[7];
    const float* lb    = (const float*)d_in[8];
    const int*   isamp = (const int*)d_in[9];
    float* out = (float*)d_out;

    static int attr_set = 0;
    if (!attr_set) {
        cudaFuncSetAttribute(conv_mma_kernel, cudaFuncAttributeMaxDynamicSharedMemorySize,
                             CONV_SMEM3);
        cudaFuncSetAttribute(select_attend_kernel, cudaFuncAttributeMaxDynamicSharedMemorySize,
                             FK_SMEM);
        attr_set = 1;
    }

    trig_kernel<<<(Sq * 64 + 255) / 256, 256>>>();
    rotary_kernel<<<(Bq * Sq * 32 + 255) / 256, 256>>>(query, key);
    wprep_kernel<<<(2 * 2 * 56 * ATILE_U4 + 255) / 256, 256>>>(ckw, cvw);

    dim3 cgrid(2, Bq, 2);
    conv_mma_kernel<<<cgrid, 256, CONV_SMEM3>>>(value, ckb, cvb);

    mean_kernel<<<Bq, 256>>>();
    select_attend_kernel<<<Bq * Hq, 256, FK_SMEM>>>(isamp);

    base_kernel<<<Bq, 256>>>(lw, lb, out);
    scatter_kernel<<<Bq * Hq, 128>>>(lw, out);
}

// round 16
// speedup vs baseline: 1.5974x; 1.0001x over previous
#include <cuda_runtime.h>
#include <math.h>
#include <stdint.h>

#define Bq   128
#define Sq   256
#define DMq  128
#define Hq   8
#define DKq  16
#define NTOPq 30
#define SKq  30
#define KSq  7
#define KKq  (Sq*KSq)   // 1792

// ---------------- scratch (device globals; no allocations allowed) -------------
__device__ float g_qrot [Bq*Sq*DMq];
__device__ float g_krot [Bq*Sq*DMq];
__device__ float g_kconv[Bq*Sq*DMq];
__device__ float g_vconv[Bq*Sq*DMq];
__device__ float g_mean [Bq*DMq];
__device__ float g_ot   [Bq*Hq*NTOPq*DKq];
__device__ float g_cos  [Sq*64];
__device__ float g_sin  [Sq*64];
__device__ int   g_mtop [Bq*Hq*NTOPq];

// A fragments (bf16 hi/lo), fragment-ordered: slice (z,tile,it): 512 uint4
#define ATILE_U4 512
__device__ uint4 g_Ahi[2*2*56*ATILE_U4];
__device__ uint4 g_Alo[2*2*56*ATILE_U4];

// ---------------- trig table (exact double, tiny cost) --------------------------
__global__ void trig_kernel() {
    int idx = blockIdx.x * blockDim.x + threadIdx.x;
    if (idx >= Sq * 64) return;
    int s = idx >> 6, i = idx & 63;
    double p  = pow(10000.0, (double)(2 * i) / 128.0);
    float  pf = (float)p;
    float  freq = 1.0f / pf;
    float  ang  = (float)s * freq;
    g_cos[idx] = (float)cos((double)ang);
    g_sin[idx] = (float)sin((double)ang);
}

// ---------------- rotary on q and k (float4 = 2 pairs per thread) ---------------
__global__ void rotary_kernel(const float* __restrict__ q, const float* __restrict__ k) {
    int idx = blockIdx.x * blockDim.x + threadIdx.x;
    if (idx >= Bq * Sq * 32) return;
    int i4 = idx & 31;
    int bs = idx >> 5;
    int s  = bs & (Sq - 1);
    const float2* c2 = reinterpret_cast<const float2*>(g_cos + s * 64 + 2 * i4);
    const float2* s2 = reinterpret_cast<const float2*>(g_sin + s * 64 + 2 * i4);
    float2 cc = *c2, ss = *s2;
    size_t base = (size_t)bs * DMq + 4 * i4;
    float4 qv = *reinterpret_cast<const float4*>(q + base);
    float4 kv = *reinterpret_cast<const float4*>(k + base);
    float4 qo, ko;
    qo.x = qv.x * cc.x - qv.y * ss.x;  qo.y = qv.x * ss.x + qv.y * cc.x;
    qo.z = qv.z * cc.y - qv.w * ss.y;  qo.w = qv.z * ss.y + qv.w * cc.y;
    ko.x = kv.x * cc.x - kv.y * ss.x;  ko.y = kv.x * ss.x + kv.y * cc.x;
    ko.z = kv.z * cc.y - kv.w * ss.y;  ko.w = kv.z * ss.y + kv.w * cc.y;
    *reinterpret_cast<float4*>(g_qrot + base) = qo;
    *reinterpret_cast<float4*>(g_krot + base) = ko;
}

// ---------------- bf16 split helpers --------------------------------------------
__device__ __forceinline__ void split_pack(float ve, float vo, uint32_t& h, uint32_t& l) {
    asm("cvt.rn.bf16x2.f32 %0, %1, %2;" : "=r"(h) : "f"(vo), "f"(ve));
    float fe = __uint_as_float(h << 16);
    float fo = __uint_as_float(h & 0xFFFF0000u);
    float le = ve - fe, lo = vo - fo;
    asm("cvt.rn.bf16x2.f32 %0, %1, %2;" : "=r"(l) : "f"(lo), "f"(le));
}
__device__ __forceinline__ void mma_bf16(float* d, const uint32_t* a,
                                         uint32_t b0, uint32_t b1) {
    asm volatile(
        "mma.sync.aligned.m16n8k16.row.col.f32.bf16.bf16.f32 "
        "{%0,%1,%2,%3}, {%4,%5,%6,%7}, {%8,%9}, {%0,%1,%2,%3};"
        : "+f"(d[0]), "+f"(d[1]), "+f"(d[2]), "+f"(d[3])
        : "r"(a[0]), "r"(a[1]), "r"(a[2]), "r"(a[3]), "r"(b0), "r"(b1));
}

#define CP_ASYNC16(dst_u32, src_ptr) \
    asm volatile("cp.async.cg.shared.global [%0], [%1], 16;" :: "r"(dst_u32), "l"(src_ptr))
#define CP_COMMIT()  asm volatile("cp.async.commit_group;")
#define CP_WAIT0()   asm volatile("cp.async.wait_group 0;")

__device__ __forceinline__ uint32_t smem_u32(const void* p) {
    uint32_t a;
    asm("{ .reg .u64 t; cvta.to.shared.u64 t, %1; cvt.u32.u64 %0, t; }" : "=r"(a) : "l"(p));
    return a;
}

// ---------------- w -> bf16 hi/lo fragments (run once per launch) ----------------
__global__ void wprep_kernel(const float* __restrict__ wk, const float* __restrict__ wv) {
    int i = blockIdx.x * 256 + threadIdx.x;
    if (i >= 2 * 2 * 56 * ATILE_U4) return;
    int lane = i & 31;
    int i2 = i >> 5;
    int m  = i2 & 7;
    int i3 = i2 >> 3;
    int s  = i3 & 1;
    int i4 = i3 >> 1;
    int it = i4 % 56;
    int i5 = i4 / 56;
    int tile = i5 & 1;
    int z    = i5 >> 1;

    const float* w = (z == 0) ? wk : wv;
    int r  = lane >> 2, c = lane & 3;
    int so = tile * 128 + m * 16 + r;
    int k0 = it * 32 + s * 16 + 2 * c;

    const float* r0p = w + (size_t)so * KKq;
    const float* r8p = w + (size_t)(so + 8) * KKq;

    uint32_t h0, l0, h1, l1, h2, l2, h3, l3;
    split_pack(r0p[k0],     r0p[k0 + 1], h0, l0);
    split_pack(r8p[k0],     r8p[k0 + 1], h1, l1);
    split_pack(r0p[k0 + 8], r0p[k0 + 9], h2, l2);
    split_pack(r8p[k0 + 8], r8p[k0 + 9], h3, l3);
    g_Ahi[i] = make_uint4(h0, h1, h2, h3);
    g_Alo[i] = make_uint4(l0, l1, l2, l3);
}

// ================= conv as mma.sync bf16 GEMM (3-split) =========================
// Round-8 pipeline + CTA phase skew (odd CTAs process chunks in reverse order)
// + fused mean: z==1 CTAs atomicAdd per-column partial sums of vconv into g_mean.
#define SA_BUF_B 16384
#define SB_OFF   (2 * SA_BUF_B)            // 32768
#define SB_BUF_B 16384
#define XW_OFF   (SB_OFF + 2 * SB_BUF_B)   // 65536
#define XW_BUF_B (6 * 136 * 4)             // 3264
#define CONV_SMEM3 (XW_OFF + 2 * XW_BUF_B) // 72064

__global__ void __launch_bounds__(256, 2)
conv_mma_kernel(const float* __restrict__ vin,
                const float* __restrict__ bk, const float* __restrict__ bv) {
    extern __shared__ __align__(16) char smem[];

    const int so_t = blockIdx.x;
    const int b    = blockIdx.y;
    const int z    = blockIdx.z;
    const int tid  = threadIdx.x;
    const int lane = tid & 31;
    const int wid  = tid >> 5;
    const int wm   = wid & 3;
    const int wn   = wid >> 2;
    const int dir  = (so_t + b + z) & 1;   // 1 -> reverse chunk order

    const float* __restrict__ xb = ((z == 0) ? (const float*)g_krot : vin)
                                   + (size_t)b * Sq * DMq;
    float* __restrict__ yb       = ((z == 0) ? g_kconv : g_vconv) + (size_t)b * Sq * DMq;
    const float* __restrict__ bias = (z == 0) ? bk : bv;

    const uint4* gAh = g_Ahi + (size_t)((z * 2 + so_t) * 56) * ATILE_U4;
    const uint4* gAl = g_Alo + (size_t)((z * 2 + so_t) * 56) * ATILE_U4;

    const uint32_t sbase = smem_u32(smem);

    // ---- B staging role constants ----
    const int cp   = tid & 15;
    const int drow = tid >> 4;
    const int sS   = cp >> 3;
    const int cS   = cp & 3;
    const int whi  = (cp >> 2) & 1;
    const int laneF = ((drow & 7) << 2) | cS;
    const int pn0   = drow >> 3;
    const int wbh = (sS ? 8 : 0) + whi * 4;
    const int wbl = (sS ? 0 : 8) + whi * 4;
    const uint32_t b_thr_off = (uint32_t)(SB_OFF + ((sS * 16 + pn0) * 32 + laneF) * 16);

    // zero the permanent pad cols (2..7) of xw, both buffers
    if (tid < 72) {
        int p  = tid / 36;
        int rm = tid - p * 36;
        int r  = rm / 6;
        int c  = 2 + (rm - r * 6);
        *(float*)(smem + XW_OFF + p * XW_BUF_B + (r * 136 + c) * 4) = 0.f;
    }

    float acc[2][8][4];
#pragma unroll
    for (int i = 0; i < 2; i++)
#pragma unroll
        for (int j = 0; j < 8; j++)
#pragma unroll
            for (int q = 0; q < 4; q++) acc[i][j][q] = 0.f;

    // ---- prologue: cp.async A chunk c(0) + xw rows for chunk c(0) ----
    {
        const int c0 = dir ? 55 : 0;
        const uint4* sH = gAh + (size_t)c0 * ATILE_U4;
        const uint4* sL = gAl + (size_t)c0 * ATILE_U4;
#pragma unroll
        for (int r = 0; r < 2; r++) {
            int i = tid + 256 * r;
            CP_ASYNC16(sbase + i * 16,        sH + i);
            CP_ASYNC16(sbase + 8192 + i * 16, sL + i);
        }
        int si0 = (32 * c0) / 7;
        if (tid < 192) {
            int r = tid >> 5, q = tid & 31;
            int gr = si0 + r;
            if (gr < Sq) {
                uint32_t dst = sbase + XW_OFF + (uint32_t)((r * 136 + 8 + 4 * q) * 4);
                CP_ASYNC16(dst, xb + (size_t)gr * DMq + 4 * q);
            }
        }
        CP_COMMIT();
    }

#pragma unroll 1
    for (int it = 0; it < 56; it++) {
        const int cur = it & 1;
        const int c   = dir ? (55 - it) : it;

        CP_WAIT0();
        __syncthreads();

        // ---- stage B[cur] from xw[cur] for chunk c ----
        {
            const float* xwb = (const float*)(smem + XW_OFF + cur * XW_BUF_B);
            int base = 32 * c;
            int si0  = base / 7;
            int kkA  = base + 2 * cp;
            int siA  = kkA / 7, tA = kkA - 7 * siA;
            int kkB  = kkA + 1;
            int siB  = kkB / 7, tB = kkB - 7 * siB;
            const float* peB = xwb + (siA - si0) * 136 + tA + 2 + drow;
            const float* poB = xwb + (siB - si0) * 136 + tB + 2 + drow;
            char* bdst = smem + b_thr_off + cur * SB_BUF_B;
#pragma unroll
            for (int j = 0; j < 8; j++) {
                uint32_t h, l;
                split_pack(peB[16 * j], poB[16 * j], h, l);
                *(uint32_t*)(bdst + j * 1024 + wbh) = h;
                *(uint32_t*)(bdst + j * 1024 + wbl) = l;
            }
        }

        // ---- issue next chunk's copies (A + xw) for chunk c(it+1) ----
        if (it < 55) {
            const int cn = dir ? (54 - it) : (it + 1);
            const uint4* sH = gAh + (size_t)cn * ATILE_U4;
            const uint4* sL = gAl + (size_t)cn * ATILE_U4;
            uint32_t dstA = sbase + (cur ^ 1) * SA_BUF_B;
#pragma unroll
            for (int r = 0; r < 2; r++) {
                int i = tid + 256 * r;
                CP_ASYNC16(dstA + i * 16,        sH + i);
                CP_ASYNC16(dstA + 8192 + i * 16, sL + i);
            }
            int si0n = (32 * cn) / 7;
            if (tid < 192) {
                int r = tid >> 5, q = tid & 31;
                int gr = si0n + r;
                if (gr < Sq) {
                    uint32_t dst = sbase + XW_OFF + (cur ^ 1) * XW_BUF_B
                                 + (uint32_t)((r * 136 + 8 + 4 * q) * 4);
                    CP_ASYNC16(dst, xb + (size_t)gr * DMq + 4 * q);
                }
            }
            CP_COMMIT();
        }
        __syncthreads();

        // ---- MMA phase ----
        const char* abase = smem + cur * SA_BUF_B;
        const char* bbase = smem + SB_OFF + cur * SB_BUF_B;
#pragma unroll
        for (int s = 0; s < 2; s++) {
            uint4 AH[2], AL[2];
#pragma unroll
            for (int mt = 0; mt < 2; mt++) {
                int fi = ((s * 8 + wm * 2 + mt) * 32 + lane) * 16;
                AH[mt] = *(const uint4*)(abase + fi);
                AL[mt] = *(const uint4*)(abase + 8192 + fi);
            }
#pragma unroll
            for (int p = 0; p < 8; p++) {
                const uint4 F = *(const uint4*)(
                    bbase + ((s * 16 + wn * 8 + p) * 32 + lane) * 16);
                const uint32_t bh0 = s ? F.z : F.x;
                const uint32_t bh1 = s ? F.w : F.y;
                const uint32_t bl0 = s ? F.x : F.z;
                const uint32_t bl1 = s ? F.y : F.w;
                mma_bf16(acc[0][p], (const uint32_t*)&AH[0], bh0, bh1);
                mma_bf16(acc[1][p], (const uint32_t*)&AH[1], bh0, bh1);
                mma_bf16(acc[0][p], (const uint32_t*)&AH[0], bl0, bl1);
                mma_bf16(acc[1][p], (const uint32_t*)&AH[1], bl0, bl1);
                mma_bf16(acc[0][p], (const uint32_t*)&AL[0], bh0, bh1);
                mma_bf16(acc[1][p], (const uint32_t*)&AL[1], bh0, bh1);
            }
        }
    }

    // ---- epilogue (+ fused column partial sums -> g_mean for z==1) ----
    const int rbase = so_t * 128 + wm * 32 + (lane >> 2);
    const int cb    = wn * 64 + (lane & 3) * 2;
    float bsum = 0.f;
    if (z == 1)
        bsum = bias[rbase] + bias[rbase + 8] + bias[rbase + 16] + bias[rbase + 24];
#pragma unroll
    for (int mt = 0; mt < 2; mt++) {
        int row = rbase + mt * 16;
        float bA = bias[row], bB = bias[row + 8];
#pragma unroll
        for (int p = 0; p < 8; p++) {
            int col = cb + p * 8;
            float2 v0 = make_float2(acc[mt][p][0] + bA, acc[mt][p][1] + bA);
            float2 v1 = make_float2(acc[mt][p][2] + bB, acc[mt][p][3] + bB);
            *reinterpret_cast<float2*>(&yb[(size_t)row * DMq + col])       = v0;
            *reinterpret_cast<float2*>(&yb[(size_t)(row + 8) * DMq + col]) = v1;
        }
    }
    if (z == 1) {
        float* mp = g_mean + b * DMq;
#pragma unroll
        for (int p = 0; p < 8; p++) {
            int col = cb + p * 8;
            float cA = acc[0][p][0] + acc[0][p][2] + acc[1][p][0] + acc[1][p][2] + bsum;
            float cB = acc[0][p][1] + acc[0][p][3] + acc[1][p][1] + acc[1][p][3] + bsum;
            atomicAdd(&mp[col],     cA * (1.0f / 256.0f));
            atomicAdd(&mp[col + 1], cB * (1.0f / 256.0f));
        }
    }
}

// ======= fused sampled-QK + top-30 selection + attention (one block per bh) =====
#define FK_KS   0
#define FK_VS   20480
#define FK_SI   40960
#define FK_MS   71680
#define FK_MT   72704
#define FK_SMEM 72832

__global__ void __launch_bounds__(256)
select_attend_kernel(const int* __restrict__ idxs) {
    extern __shared__ __align__(16) char fsm[];
    float* ksh  = (float*)(fsm + FK_KS);
    float* vsh  = (float*)(fsm + FK_VS);
    int*   sidx = (int*)(fsm + FK_SI);
    float* Msh  = (float*)(fsm + FK_MS);
    int*   smtop= (int*)(fsm + FK_MT);

    int bh = blockIdx.x;
    int b  = bh >> 3, h = bh & 7;
    int tid = threadIdx.x;
    int l   = tid;

#pragma unroll
    for (int rep = 0; rep < 4; rep++) {
        int i = tid + 256 * rep;
        int row = i >> 2, c = i & 3;
        size_t g = ((size_t)b * Sq + row) * DMq + h * DKq + 4 * c;
        *reinterpret_cast<float4*>(&ksh[row * 20 + 4 * c]) =
            *reinterpret_cast<const float4*>(&g_kconv[g]);
        *reinterpret_cast<float4*>(&vsh[row * 20 + 4 * c]) =
            *reinterpret_cast<const float4*>(&g_vconv[g]);
    }
    for (int i = tid; i < (Sq * SKq) / 4; i += 256)
        reinterpret_cast<int4*>(sidx)[i] = reinterpret_cast<const int4*>(idxs)[i];
    __syncthreads();

    // ---- M[l] = max - mean of sampled QK ----
    {
        const float4* qp = reinterpret_cast<const float4*>(
            g_qrot + ((size_t)b * Sq + l) * DMq + h * DKq);
        float4 q0 = qp[0], q1 = qp[1], q2 = qp[2], q3 = qp[3];

        float mx = -3.402823466e38f;
        float sum = 0.f;
#pragma unroll 1
        for (int s = 0; s < SKq; s++) {
            int j = sidx[l * SKq + s];
            const float4* kp = reinterpret_cast<const float4*>(&ksh[j * 20]);
            float4 k0 = kp[0], k1 = kp[1], k2 = kp[2], k3 = kp[3];
            float dot = 0.f;
            dot += q0.x * k0.x; dot += q0.y * k0.y; dot += q0.z * k0.z; dot += q0.w * k0.w;
            dot += q1.x * k1.x; dot += q1.y * k1.y; dot += q1.z * k1.z; dot += q1.w * k1.w;
            dot += q2.x * k2.x; dot += q2.y * k2.y; dot += q2.z * k2.z; dot += q2.w * k2.w;
            dot += q3.x * k3.x; dot += q3.y * k3.y; dot += q3.z * k3.z; dot += q3.w * k3.w;
            mx = fmaxf(mx, dot);
            sum += dot;
        }
        Msh[l] = mx - sum * (1.0f / 30.0f);
    }
    __syncthreads();

    if (l < 32) {
        float mv[8];
#pragma unroll
        for (int j = 0; j < 8; j++) mv[j] = Msh[l + 32 * j];
#pragma unroll 1
        for (int u = 0; u < NTOPq; u++) {
            float bvv = mv[0];
            int   bj  = 0;
#pragma unroll
            for (int j = 1; j < 8; j++)
                if (mv[j] > bvv) { bvv = mv[j]; bj = j; }
            int bidx = l + 32 * bj;
#pragma unroll
            for (int off = 16; off > 0; off >>= 1) {
                float ov = __shfl_xor_sync(0xffffffffu, bvv, off);
                int   oi = __shfl_xor_sync(0xffffffffu, bidx, off);
                if (ov > bvv || (ov == bvv && oi < bidx)) { bvv = ov; bidx = oi; }
            }
            if (l == 0) { g_mtop[bh * NTOPq + u] = bidx; smtop[u] = bidx; }
            if ((bidx & 31) == l) {
                int slot = bidx >> 5;
#pragma unroll
                for (int j = 0; j < 8; j++)
                    if (j == slot) mv[j] = -3.402823466e38f;
            }
        }
    }
    __syncthreads();

    const int warp = tid >> 5;
    const int lane = tid & 31;

#pragma unroll 1
    for (int jj = 0; jj < 4; jj++) {
        int u = warp + 8 * jj;
        if (u >= NTOPq) break;
        int lsel = smtop[u];
        float qv = g_qrot[((size_t)b * Sq + lsel) * DMq + h * DKq + (lane & 15)];
        float qq[16];
#pragma unroll
        for (int i = 0; i < 16; i++) qq[i] = __shfl_sync(0xffffffffu, qv, i);

        float dot[8];
#pragma unroll
        for (int m = 0; m < 8; m++) {
            const float4* kr = reinterpret_cast<const float4*>(&ksh[(lane + 32 * m) * 20]);
            float4 k0 = kr[0], k1 = kr[1], k2 = kr[2], k3 = kr[3];
            float dd = 0.f;
            dd += qq[0]  * k0.x; dd += qq[1]  * k0.y; dd += qq[2]  * k0.z; dd += qq[3]  * k0.w;
            dd += qq[4]  * k1.x; dd += qq[5]  * k1.y; dd += qq[6]  * k1.z; dd += qq[7]  * k1.w;
            dd += qq[8]  * k2.x; dd += qq[9]  * k2.y; dd += qq[10] * k2.z; dd += qq[11] * k2.w;
            dd += qq[12] * k3.x; dd += qq[13] * k3.y; dd += qq[14] * k3.z; dd += qq[15] * k3.w;
            dot[m] = dd;
        }
        float mx = -3.402823466e38f;
#pragma unroll
        for (int m = 0; m < 8; m++) { dot[m] *= 0.25f; mx = fmaxf(mx, dot[m]); }
#pragma unroll
        for (int off = 16; off > 0; off >>= 1)
            mx = fmaxf(mx, __shfl_xor_sync(0xffffffffu, mx, off));
        float p[8];
        float sum = 0.f;
#pragma unroll
        for (int m = 0; m < 8; m++) { p[m] = expf(dot[m] - mx); sum += p[m]; }
#pragma unroll
        for (int off = 16; off > 0; off >>= 1)
            sum += __shfl_xor_sync(0xffffffffu, sum, off);

        float o[16];
#pragma unroll
        for (int d = 0; d < 16; d++) o[d] = 0.f;
#pragma unroll
        for (int m = 0; m < 8; m++) {
            float pm = p[m];
            const float4* vr = reinterpret_cast<const float4*>(&vsh[(lane + 32 * m) * 20]);
#pragma unroll
            for (int c = 0; c < 4; c++) {
                float4 vv = vr[c];
                o[4*c]   += pm * vv.x;
                o[4*c+1] += pm * vv.y;
                o[4*c+2] += pm * vv.z;
                o[4*c+3] += pm * vv.w;
            }
        }
#pragma unroll
        for (int off = 16; off > 0; off >>= 1)
#pragma unroll
            for (int d = 0; d < 16; d++)
                o[d] += __shfl_xor_sync(0xffffffffu, o[d], off);

        if (lane == 0) {
            float inv = 1.0f / sum;
            float* op = g_ot + ((size_t)bh * NTOPq + u) * DKq;
#pragma unroll
            for (int d4 = 0; d4 < 4; d4++) {
                float4 v = make_float4(o[4*d4]*inv, o[4*d4+1]*inv, o[4*d4+2]*inv, o[4*d4+3]*inv);
                *reinterpret_cast<float4*>(op + 4 * d4) = v;
            }
        }
    }
}

// ---------------- base output: out[b,s,:] = mean(b) @ W^T + bias ------------------
__global__ void base_kernel(const float* __restrict__ w, const float* __restrict__ bias,
                            float* __restrict__ out) {
    __shared__ float meansh[DMq];
    __shared__ float baseo[DMq];
    int b = blockIdx.x;
    int tid = threadIdx.x;
    if (tid < DMq) meansh[tid] = g_mean[b * DMq + tid];
    __syncthreads();
    if (tid < DMq) {
        const float4* wr = reinterpret_cast<const float4*>(w + (size_t)tid * DMq);
        float dot = 0.f;
#pragma unroll
        for (int q = 0; q < 32; q++) {
            float4 wv = wr[q];
            dot += wv.x * meansh[4*q] + wv.y * meansh[4*q+1]
                 + wv.z * meansh[4*q+2] + wv.w * meansh[4*q+3];
        }
        baseo[tid] = dot + bias[tid];
    }
    __syncthreads();
    const float4* b4 = reinterpret_cast<const float4*>(baseo);
    float4* o4 = reinterpret_cast<float4*>(out + (size_t)b * Sq * DMq);
#pragma unroll 4
    for (int k = 0; k < 32; k++) {
        int idx = tid + 256 * k;
        int s = idx >> 5, q = idx & 31;
        o4[s * 32 + q] = b4[q];
    }
}

// ---------------- scatter corrections: out[b,s,:] += (ot - mean_h) @ Wh^T --------
__global__ void scatter_kernel(const float* __restrict__ w, float* __restrict__ out) {
    int bh = blockIdx.x;
    int b  = bh >> 3, h = bh & 7;
    int j  = threadIdx.x;
    int lane = j & 31;

    float wh[16];
    const float4* wr = reinterpret_cast<const float4*>(w + (size_t)j * DMq + h * DKq);
#pragma unroll
    for (int q = 0; q < 4; q++) {
        float4 v = wr[q];
        wh[4*q] = v.x; wh[4*q+1] = v.y; wh[4*q+2] = v.z; wh[4*q+3] = v.w;
    }
    float msl = (lane < 16) ? g_mean[b * DMq + h * DKq + lane] : 0.f;
    float mi[16];
#pragma unroll
    for (int i = 0; i < 16; i++) mi[i] = __shfl_sync(0xffffffffu, msl, i);

#pragma unroll 1
    for (int u = 0; u < NTOPq; u++) {
        int s = g_mtop[bh * NTOPq + u];
        float otv = (lane < 16) ? g_ot[((size_t)bh * NTOPq + u) * DKq + lane] : 0.f;
        float corr = 0.f;
#pragma unroll
        for (int i = 0; i < 16; i++)
            corr += (__shfl_sync(0xffffffffu, otv, i) - mi[i]) * wh[i];
        atomicAdd(&out[((size_t)b * Sq + s) * DMq + j], corr);
    }
}

// -------------------------------------------------------------------------------
extern "C" void kernel_launch(void* const* d_in, const int* in_sizes, int n_in,
                              void* d_out, int out_size) {
    const float* query = (const float*)d_in[0];
    const float* key   = (const float*)d_in[1];
    const float* value = (const float*)d_in[2];
    const float* ckw   = (const float*)d_in[3];
    const float* ckb   = (const float*)d_in[4];
    const float* cvw   = (const float*)d_in[5];
    const float* cvb   = (const float*)d_in[6];
    const float* lw    = (const float*)d_in[7];
    const float* lb    = (const float*)d_in[8];
    const int*   isamp = (const int*)d_in[9];
    float* out = (float*)d_out;

    static int attr_set = 0;
    static void* mean_ptr = nullptr;
    if (!attr_set) {
        cudaFuncSetAttribute(conv_mma_kernel, cudaFuncAttributeMaxDynamicSharedMemorySize,
                             CONV_SMEM3);
        cudaFuncSetAttribute(select_attend_kernel, cudaFuncAttributeMaxDynamicSharedMemorySize,
                             FK_SMEM);
        cudaGetSymbolAddress(&mean_ptr, g_mean);
        attr_set = 1;
    }

    trig_kernel<<<(Sq * 64 + 255) / 256, 256>>>();
    rotary_kernel<<<(Bq * Sq * 32 + 255) / 256, 256>>>(query, key);
    wprep_kernel<<<(2 * 2 * 56 * ATILE_U4 + 255) / 256, 256>>>(ckw, cvw);
    cudaMemsetAsync(mean_ptr, 0, (size_t)Bq * DMq * sizeof(float));

    dim3 cgrid(2, Bq, 2);
    conv_mma_kernel<<<cgrid, 256, CONV_SMEM3>>>(value, ckb, cvb);

    select_attend_kernel<<<Bq * Hq, 256, FK_SMEM>>>(isamp);

    base_kernel<<<Bq, 256>>>(lw, lb, out);
    scatter_kernel<<<Bq * Hq, 128>>>(lw, out);
}

// round 17
// speedup vs baseline: 1.6531x; 1.0349x over previous
#include <cuda_runtime.h>
#include <math.h>
#include <stdint.h>

#define Bq   128
#define Sq   256
#define DMq  128
#define Hq   8
#define DKq  16
#define NTOPq 30
#define SKq  30
#define KSq  7
#define KKq  (Sq*KSq)   // 1792

// ---------------- scratch (device globals; no allocations allowed) -------------
__device__ float g_qrot [Bq*Sq*DMq];
__device__ float g_krot [Bq*Sq*DMq];
__device__ float g_kconv[Bq*Sq*DMq];
__device__ float g_vconv[Bq*Sq*DMq];
__device__ float g_mean [Bq*DMq];
__device__ float g_ot   [Bq*Hq*NTOPq*DKq];
__device__ float g_cos  [Sq*64];
__device__ float g_sin  [Sq*64];
__device__ int   g_mtop [Bq*Hq*NTOPq];

// A fragments (bf16 hi/lo), fragment-ordered: slice (z,tile,it): 512 uint4
#define ATILE_U4 512
__device__ uint4 g_Ahi[2*2*56*ATILE_U4];
__device__ uint4 g_Alo[2*2*56*ATILE_U4];

// ---------------- trig table (exact double, tiny cost) --------------------------
__global__ void trig_kernel() {
    int idx = blockIdx.x * blockDim.x + threadIdx.x;
    if (idx >= Sq * 64) return;
    int s = idx >> 6, i = idx & 63;
    double p  = pow(10000.0, (double)(2 * i) / 128.0);
    float  pf = (float)p;
    float  freq = 1.0f / pf;
    float  ang  = (float)s * freq;
    g_cos[idx] = (float)cos((double)ang);
    g_sin[idx] = (float)sin((double)ang);
}

// ---------------- rotary on q and k (float4 = 2 pairs per thread) ---------------
__global__ void rotary_kernel(const float* __restrict__ q, const float* __restrict__ k) {
    int idx = blockIdx.x * blockDim.x + threadIdx.x;
    if (idx >= Bq * Sq * 32) return;
    int i4 = idx & 31;
    int bs = idx >> 5;
    int s  = bs & (Sq - 1);
    const float2* c2 = reinterpret_cast<const float2*>(g_cos + s * 64 + 2 * i4);
    const float2* s2 = reinterpret_cast<const float2*>(g_sin + s * 64 + 2 * i4);
    float2 cc = *c2, ss = *s2;
    size_t base = (size_t)bs * DMq + 4 * i4;
    float4 qv = *reinterpret_cast<const float4*>(q + base);
    float4 kv = *reinterpret_cast<const float4*>(k + base);
    float4 qo, ko;
    qo.x = qv.x * cc.x - qv.y * ss.x;  qo.y = qv.x * ss.x + qv.y * cc.x;
    qo.z = qv.z * cc.y - qv.w * ss.y;  qo.w = qv.z * ss.y + qv.w * cc.y;
    ko.x = kv.x * cc.x - kv.y * ss.x;  ko.y = kv.x * ss.x + kv.y * cc.x;
    ko.z = kv.z * cc.y - kv.w * ss.y;  ko.w = kv.z * ss.y + kv.w * cc.y;
    *reinterpret_cast<float4*>(g_qrot + base) = qo;
    *reinterpret_cast<float4*>(g_krot + base) = ko;
}

// ---------------- bf16 split helpers --------------------------------------------
__device__ __forceinline__ void split_pack(float ve, float vo, uint32_t& h, uint32_t& l) {
    asm("cvt.rn.bf16x2.f32 %0, %1, %2;" : "=r"(h) : "f"(vo), "f"(ve));
    float fe = __uint_as_float(h << 16);
    float fo = __uint_as_float(h & 0xFFFF0000u);
    float le = ve - fe, lo = vo - fo;
    asm("cvt.rn.bf16x2.f32 %0, %1, %2;" : "=r"(l) : "f"(lo), "f"(le));
}
__device__ __forceinline__ void mma_bf16(float* d, const uint32_t* a,
                                         uint32_t b0, uint32_t b1) {
    asm volatile(
        "mma.sync.aligned.m16n8k16.row.col.f32.bf16.bf16.f32 "
        "{%0,%1,%2,%3}, {%4,%5,%6,%7}, {%8,%9}, {%0,%1,%2,%3};"
        : "+f"(d[0]), "+f"(d[1]), "+f"(d[2]), "+f"(d[3])
        : "r"(a[0]), "r"(a[1]), "r"(a[2]), "r"(a[3]), "r"(b0), "r"(b1));
}

#define CP_ASYNC16(dst_u32, src_ptr) \
    asm volatile("cp.async.cg.shared.global [%0], [%1], 16;" :: "r"(dst_u32), "l"(src_ptr))
#define CP_COMMIT()  asm volatile("cp.async.commit_group;")
#define CP_WAIT0()   asm volatile("cp.async.wait_group 0;")

__device__ __forceinline__ uint32_t smem_u32(const void* p) {
    uint32_t a;
    asm("{ .reg .u64 t; cvta.to.shared.u64 t, %1; cvt.u32.u64 %0, t; }" : "=r"(a) : "l"(p));
    return a;
}

// ---------------- w -> bf16 hi/lo fragments (run once per launch) ----------------
__global__ void wprep_kernel(const float* __restrict__ wk, const float* __restrict__ wv) {
    int i = blockIdx.x * 256 + threadIdx.x;
    if (i >= 2 * 2 * 56 * ATILE_U4) return;
    int lane = i & 31;
    int i2 = i >> 5;
    int m  = i2 & 7;
    int i3 = i2 >> 3;
    int s  = i3 & 1;
    int i4 = i3 >> 1;
    int it = i4 % 56;
    int i5 = i4 / 56;
    int tile = i5 & 1;
    int z    = i5 >> 1;

    const float* w = (z == 0) ? wk : wv;
    int r  = lane >> 2, c = lane & 3;
    int so = tile * 128 + m * 16 + r;
    int k0 = it * 32 + s * 16 + 2 * c;

    const float* r0p = w + (size_t)so * KKq;
    const float* r8p = w + (size_t)(so + 8) * KKq;

    uint32_t h0, l0, h1, l1, h2, l2, h3, l3;
    split_pack(r0p[k0],     r0p[k0 + 1], h0, l0);
    split_pack(r8p[k0],     r8p[k0 + 1], h1, l1);
    split_pack(r0p[k0 + 8], r0p[k0 + 9], h2, l2);
    split_pack(r8p[k0 + 8], r8p[k0 + 9], h3, l3);
    g_Ahi[i] = make_uint4(h0, h1, h2, h3);
    g_Alo[i] = make_uint4(l0, l1, l2, l3);
}

// ================= conv as mma.sync bf16 GEMM (3-split) =========================
// Round-8 pipeline (forward chunk order) + fused mean for z==1.
#define SA_BUF_B 16384
#define SB_OFF   (2 * SA_BUF_B)            // 32768
#define SB_BUF_B 16384
#define XW_OFF   (SB_OFF + 2 * SB_BUF_B)   // 65536
#define XW_BUF_B (6 * 136 * 4)             // 3264
#define CONV_SMEM3 (XW_OFF + 2 * XW_BUF_B) // 72064

__global__ void __launch_bounds__(256, 2)
conv_mma_kernel(const float* __restrict__ vin,
                const float* __restrict__ bk, const float* __restrict__ bv) {
    extern __shared__ __align__(16) char smem[];

    const int so_t = blockIdx.x;
    const int b    = blockIdx.y;
    const int z    = blockIdx.z;
    const int tid  = threadIdx.x;
    const int lane = tid & 31;
    const int wid  = tid >> 5;
    const int wm   = wid & 3;
    const int wn   = wid >> 2;

    const float* __restrict__ xb = ((z == 0) ? (const float*)g_krot : vin)
                                   + (size_t)b * Sq * DMq;
    float* __restrict__ yb       = ((z == 0) ? g_kconv : g_vconv) + (size_t)b * Sq * DMq;
    const float* __restrict__ bias = (z == 0) ? bk : bv;

    const uint4* gAh = g_Ahi + (size_t)((z * 2 + so_t) * 56) * ATILE_U4;
    const uint4* gAl = g_Alo + (size_t)((z * 2 + so_t) * 56) * ATILE_U4;

    const uint32_t sbase = smem_u32(smem);

    // ---- B staging role constants ----
    const int cp   = tid & 15;
    const int drow = tid >> 4;
    const int sS   = cp >> 3;
    const int cS   = cp & 3;
    const int whi  = (cp >> 2) & 1;
    const int laneF = ((drow & 7) << 2) | cS;
    const int pn0   = drow >> 3;
    const int wbh = (sS ? 8 : 0) + whi * 4;
    const int wbl = (sS ? 0 : 8) + whi * 4;
    const uint32_t b_thr_off = (uint32_t)(SB_OFF + ((sS * 16 + pn0) * 32 + laneF) * 16);

    // zero the permanent pad cols (2..7) of xw, both buffers
    if (tid < 72) {
        int p  = tid / 36;
        int rm = tid - p * 36;
        int r  = rm / 6;
        int c  = 2 + (rm - r * 6);
        *(float*)(smem + XW_OFF + p * XW_BUF_B + (r * 136 + c) * 4) = 0.f;
    }

    float acc[2][8][4];
#pragma unroll
    for (int i = 0; i < 2; i++)
#pragma unroll
        for (int j = 0; j < 8; j++)
#pragma unroll
            for (int q = 0; q < 4; q++) acc[i][j][q] = 0.f;

    // ---- prologue: cp.async A chunk 0 + xw rows for chunk 0 ----
    {
#pragma unroll
        for (int r = 0; r < 2; r++) {
            int i = tid + 256 * r;
            CP_ASYNC16(sbase + i * 16,        gAh + i);
            CP_ASYNC16(sbase + 8192 + i * 16, gAl + i);
        }
        if (tid < 192) {
            int r = tid >> 5, q = tid & 31;
            uint32_t dst = sbase + XW_OFF + (uint32_t)((r * 136 + 8 + 4 * q) * 4);
            CP_ASYNC16(dst, xb + (size_t)r * DMq + 4 * q);
        }
        CP_COMMIT();
    }

#pragma unroll 1
    for (int it = 0; it < 56; it++) {
        const int cur = it & 1;

        CP_WAIT0();
        __syncthreads();

        // ---- stage B[cur] from xw[cur] ----
        {
            const float* xwb = (const float*)(smem + XW_OFF + cur * XW_BUF_B);
            int base = 32 * it;
            int si0  = base / 7;
            int kkA  = base + 2 * cp;
            int siA  = kkA / 7, tA = kkA - 7 * siA;
            int kkB  = kkA + 1;
            int siB  = kkB / 7, tB = kkB - 7 * siB;
            const float* peB = xwb + (siA - si0) * 136 + tA + 2 + drow;
            const float* poB = xwb + (siB - si0) * 136 + tB + 2 + drow;
            char* bdst = smem + b_thr_off + cur * SB_BUF_B;
#pragma unroll
            for (int j = 0; j < 8; j++) {
                uint32_t h, l;
                split_pack(peB[16 * j], poB[16 * j], h, l);
                *(uint32_t*)(bdst + j * 1024 + wbh) = h;
                *(uint32_t*)(bdst + j * 1024 + wbl) = l;
            }
        }

        // ---- issue next chunk's copies (A + xw) ----
        if (it < 55) {
            const uint4* sH = gAh + (size_t)(it + 1) * ATILE_U4;
            const uint4* sL = gAl + (size_t)(it + 1) * ATILE_U4;
            uint32_t dstA = sbase + (cur ^ 1) * SA_BUF_B;
#pragma unroll
            for (int r = 0; r < 2; r++) {
                int i = tid + 256 * r;
                CP_ASYNC16(dstA + i * 16,        sH + i);
                CP_ASYNC16(dstA + 8192 + i * 16, sL + i);
            }
            int si0n = (32 * (it + 1)) / 7;
            if (tid < 192) {
                int r = tid >> 5, q = tid & 31;
                int gr = si0n + r;
                if (gr < Sq) {
                    uint32_t dst = sbase + XW_OFF + (cur ^ 1) * XW_BUF_B
                                 + (uint32_t)((r * 136 + 8 + 4 * q) * 4);
                    CP_ASYNC16(dst, xb + (size_t)gr * DMq + 4 * q);
                }
            }
            CP_COMMIT();
        }
        __syncthreads();

        // ---- MMA phase ----
        const char* abase = smem + cur * SA_BUF_B;
        const char* bbase = smem + SB_OFF + cur * SB_BUF_B;
#pragma unroll
        for (int s = 0; s < 2; s++) {
            uint4 AH[2], AL[2];
#pragma unroll
            for (int mt = 0; mt < 2; mt++) {
                int fi = ((s * 8 + wm * 2 + mt) * 32 + lane) * 16;
                AH[mt] = *(const uint4*)(abase + fi);
                AL[mt] = *(const uint4*)(abase + 8192 + fi);
            }
#pragma unroll
            for (int p = 0; p < 8; p++) {
                const uint4 F = *(const uint4*)(
                    bbase + ((s * 16 + wn * 8 + p) * 32 + lane) * 16);
                const uint32_t bh0 = s ? F.z : F.x;
                const uint32_t bh1 = s ? F.w : F.y;
                const uint32_t bl0 = s ? F.x : F.z;
                const uint32_t bl1 = s ? F.y : F.w;
                mma_bf16(acc[0][p], (const uint32_t*)&AH[0], bh0, bh1);
                mma_bf16(acc[1][p], (const uint32_t*)&AH[1], bh0, bh1);
                mma_bf16(acc[0][p], (const uint32_t*)&AH[0], bl0, bl1);
                mma_bf16(acc[1][p], (const uint32_t*)&AH[1], bl0, bl1);
                mma_bf16(acc[0][p], (const uint32_t*)&AL[0], bh0, bh1);
                mma_bf16(acc[1][p], (const uint32_t*)&AL[1], bh0, bh1);
            }
        }
    }

    // ---- epilogue (+ fused column partial sums -> g_mean for z==1) ----
    const int rbase = so_t * 128 + wm * 32 + (lane >> 2);
    const int cb    = wn * 64 + (lane & 3) * 2;
    float bsum = 0.f;
    if (z == 1)
        bsum = bias[rbase] + bias[rbase + 8] + bias[rbase + 16] + bias[rbase + 24];
#pragma unroll
    for (int mt = 0; mt < 2; mt++) {
        int row = rbase + mt * 16;
        float bA = bias[row], bB = bias[row + 8];
#pragma unroll
        for (int p = 0; p < 8; p++) {
            int col = cb + p * 8;
            float2 v0 = make_float2(acc[mt][p][0] + bA, acc[mt][p][1] + bA);
            float2 v1 = make_float2(acc[mt][p][2] + bB, acc[mt][p][3] + bB);
            *reinterpret_cast<float2*>(&yb[(size_t)row * DMq + col])       = v0;
            *reinterpret_cast<float2*>(&yb[(size_t)(row + 8) * DMq + col]) = v1;
        }
    }
    if (z == 1) {
        float* mp = g_mean + b * DMq;
#pragma unroll
        for (int p = 0; p < 8; p++) {
            int col = cb + p * 8;
            float cA = acc[0][p][0] + acc[0][p][2] + acc[1][p][0] + acc[1][p][2] + bsum;
            float cB = acc[0][p][1] + acc[0][p][3] + acc[1][p][1] + acc[1][p][3] + bsum;
            atomicAdd(&mp[col],     cA * (1.0f / 256.0f));
            atomicAdd(&mp[col + 1], cB * (1.0f / 256.0f));
        }
    }
}

// ======= fused sampled-QK + top-30 selection + attention (one block per bh) =====
// smem: ksh 20480 | vsh 20480 | Msh 1024 | smtop 128 -> 42112 (5 CTAs/SM)
#define FK_KS   0
#define FK_VS   20480
#define FK_MS   40960
#define FK_MT   41984
#define FK_SMEM 42112

__global__ void __launch_bounds__(256)
select_attend_kernel(const int* __restrict__ idxs) {
    extern __shared__ __align__(16) char fsm[];
    float* ksh  = (float*)(fsm + FK_KS);
    float* vsh  = (float*)(fsm + FK_VS);
    float* Msh  = (float*)(fsm + FK_MS);
    int*   smtop= (int*)(fsm + FK_MT);

    int bh = blockIdx.x;
    int b  = bh >> 3, h = bh & 7;
    int tid = threadIdx.x;
    int l   = tid;

    // preload this thread's 30 sample indices from global (contiguous 120B, L1-hot)
    int2 sidx2[15];
    {
        const int2* ip = reinterpret_cast<const int2*>(idxs + l * SKq);
#pragma unroll
        for (int i = 0; i < 15; i++) sidx2[i] = ip[i];
    }

#pragma unroll
    for (int rep = 0; rep < 4; rep++) {
        int i = tid + 256 * rep;
        int row = i >> 2, c = i & 3;
        size_t g = ((size_t)b * Sq + row) * DMq + h * DKq + 4 * c;
        *reinterpret_cast<float4*>(&ksh[row * 20 + 4 * c]) =
            *reinterpret_cast<const float4*>(&g_kconv[g]);
        *reinterpret_cast<float4*>(&vsh[row * 20 + 4 * c]) =
            *reinterpret_cast<const float4*>(&g_vconv[g]);
    }
    __syncthreads();

    // ---- M[l] = max - mean of sampled QK (fully unrolled, reg indices) ----
    {
        const float4* qp = reinterpret_cast<const float4*>(
            g_qrot + ((size_t)b * Sq + l) * DMq + h * DKq);
        float4 q0 = qp[0], q1 = qp[1], q2 = qp[2], q3 = qp[3];

        float mx = -3.402823466e38f;
        float sum = 0.f;
#pragma unroll
        for (int s = 0; s < SKq; s++) {
            int j = (s & 1) ? sidx2[s >> 1].y : sidx2[s >> 1].x;
            const float4* kp = reinterpret_cast<const float4*>(&ksh[j * 20]);
            float4 k0 = kp[0], k1 = kp[1], k2 = kp[2], k3 = kp[3];
            float dot = 0.f;
            dot += q0.x * k0.x; dot += q0.y * k0.y; dot += q0.z * k0.z; dot += q0.w * k0.w;
            dot += q1.x * k1.x; dot += q1.y * k1.y; dot += q1.z * k1.z; dot += q1.w * k1.w;
            dot += q2.x * k2.x; dot += q2.y * k2.y; dot += q2.z * k2.z; dot += q2.w * k2.w;
            dot += q3.x * k3.x; dot += q3.y * k3.y; dot += q3.z * k3.z; dot += q3.w * k3.w;
            mx = fmaxf(mx, dot);
            sum += dot;
        }
        Msh[l] = mx - sum * (1.0f / 30.0f);
    }
    __syncthreads();

    if (l < 32) {
        float mv[8];
#pragma unroll
        for (int j = 0; j < 8; j++) mv[j] = Msh[l + 32 * j];
#pragma unroll 1
        for (int u = 0; u < NTOPq; u++) {
            float bvv = mv[0];
            int   bj  = 0;
#pragma unroll
            for (int j = 1; j < 8; j++)
                if (mv[j] > bvv) { bvv = mv[j]; bj = j; }
            int bidx = l + 32 * bj;
#pragma unroll
            for (int off = 16; off > 0; off >>= 1) {
                float ov = __shfl_xor_sync(0xffffffffu, bvv, off);
                int   oi = __shfl_xor_sync(0xffffffffu, bidx, off);
                if (ov > bvv || (ov == bvv && oi < bidx)) { bvv = ov; bidx = oi; }
            }
            if (l == 0) { g_mtop[bh * NTOPq + u] = bidx; smtop[u] = bidx; }
            if ((bidx & 31) == l) {
                int slot = bidx >> 5;
#pragma unroll
                for (int j = 0; j < 8; j++)
                    if (j == slot) mv[j] = -3.402823466e38f;
            }
        }
    }
    __syncthreads();

    const int warp = tid >> 5;
    const int lane = tid & 31;

#pragma unroll 1
    for (int jj = 0; jj < 4; jj++) {
        int u = warp + 8 * jj;
        if (u >= NTOPq) break;
        int lsel = smtop[u];
        float qv = g_qrot[((size_t)b * Sq + lsel) * DMq + h * DKq + (lane & 15)];
        float qq[16];
#pragma unroll
        for (int i = 0; i < 16; i++) qq[i] = __shfl_sync(0xffffffffu, qv, i);

        float dot[8];
#pragma unroll
        for (int m = 0; m < 8; m++) {
            const float4* kr = reinterpret_cast<const float4*>(&ksh[(lane + 32 * m) * 20]);
            float4 k0 = kr[0], k1 = kr[1], k2 = kr[2], k3 = kr[3];
            float dd = 0.f;
            dd += qq[0]  * k0.x; dd += qq[1]  * k0.y; dd += qq[2]  * k0.z; dd += qq[3]  * k0.w;
            dd += qq[4]  * k1.x; dd += qq[5]  * k1.y; dd += qq[6]  * k1.z; dd += qq[7]  * k1.w;
            dd += qq[8]  * k2.x; dd += qq[9]  * k2.y; dd += qq[10] * k2.z; dd += qq[11] * k2.w;
            dd += qq[12] * k3.x; dd += qq[13] * k3.y; dd += qq[14] * k3.z; dd += qq[15] * k3.w;
            dot[m] = dd;
        }
        float mx = -3.402823466e38f;
#pragma unroll
        for (int m = 0; m < 8; m++) { dot[m] *= 0.25f; mx = fmaxf(mx, dot[m]); }
#pragma unroll
        for (int off = 16; off > 0; off >>= 1)
            mx = fmaxf(mx, __shfl_xor_sync(0xffffffffu, mx, off));
        float p[8];
        float sum = 0.f;
#pragma unroll
        for (int m = 0; m < 8; m++) { p[m] = expf(dot[m] - mx); sum += p[m]; }
#pragma unroll
        for (int off = 16; off > 0; off >>= 1)
            sum += __shfl_xor_sync(0xffffffffu, sum, off);

        float o[16];
#pragma unroll
        for (int d = 0; d < 16; d++) o[d] = 0.f;
#pragma unroll
        for (int m = 0; m < 8; m++) {
            float pm = p[m];
            const float4* vr = reinterpret_cast<const float4*>(&vsh[(lane + 32 * m) * 20]);
#pragma unroll
            for (int c = 0; c < 4; c++) {
                float4 vv = vr[c];
                o[4*c]   += pm * vv.x;
                o[4*c+1] += pm * vv.y;
                o[4*c+2] += pm * vv.z;
                o[4*c+3] += pm * vv.w;
            }
        }
#pragma unroll
        for (int off = 16; off > 0; off >>= 1)
#pragma unroll
            for (int d = 0; d < 16; d++)
                o[d] += __shfl_xor_sync(0xffffffffu, o[d], off);

        if (lane == 0) {
            float inv = 1.0f / sum;
            float* op = g_ot + ((size_t)bh * NTOPq + u) * DKq;
#pragma unroll
            for (int d4 = 0; d4 < 4; d4++) {
                float4 v = make_float4(o[4*d4]*inv, o[4*d4+1]*inv, o[4*d4+2]*inv, o[4*d4+3]*inv);
                *reinterpret_cast<float4*>(op + 4 * d4) = v;
            }
        }
    }
}

// ---------------- base output: out[b,s,:] = mean(b) @ W^T + bias ------------------
__global__ void base_kernel(const float* __restrict__ w, const float* __restrict__ bias,
                            float* __restrict__ out) {
    __shared__ float meansh[DMq];
    __shared__ float baseo[DMq];
    int b = blockIdx.x;
    int tid = threadIdx.x;
    if (tid < DMq) meansh[tid] = g_mean[b * DMq + tid];
    __syncthreads();
    if (tid < DMq) {
        const float4* wr = reinterpret_cast<const float4*>(w + (size_t)tid * DMq);
        float dot = 0.f;
#pragma unroll
        for (int q = 0; q < 32; q++) {
            float4 wv = wr[q];
            dot += wv.x * meansh[4*q] + wv.y * meansh[4*q+1]
                 + wv.z * meansh[4*q+2] + wv.w * meansh[4*q+3];
        }
        baseo[tid] = dot + bias[tid];
    }
    __syncthreads();
    const float4* b4 = reinterpret_cast<const float4*>(baseo);
    float4* o4 = reinterpret_cast<float4*>(out + (size_t)b * Sq * DMq);
#pragma unroll 4
    for (int k = 0; k < 32; k++) {
        int idx = tid + 256 * k;
        int s = idx >> 5, q = idx & 31;
        o4[s * 32 + q] = b4[q];
    }
}

// ---------------- scatter corrections: out[b,s,:] += (ot - mean_h) @ Wh^T --------
__global__ void scatter_kernel(const float* __restrict__ w, float* __restrict__ out) {
    int bh = blockIdx.x;
    int b  = bh >> 3, h = bh & 7;
    int j  = threadIdx.x;
    int lane = j & 31;

    float wh[16];
    const float4* wr = reinterpret_cast<const float4*>(w + (size_t)j * DMq + h * DKq);
#pragma unroll
    for (int q = 0; q < 4; q++) {
        float4 v = wr[q];
        wh[4*q] = v.x; wh[4*q+1] = v.y; wh[4*q+2] = v.z; wh[4*q+3] = v.w;
    }
    float msl = (lane < 16) ? g_mean[b * DMq + h * DKq + lane] : 0.f;
    float mi[16];
#pragma unroll
    for (int i = 0; i < 16; i++) mi[i] = __shfl_sync(0xffffffffu, msl, i);

#pragma unroll 1
    for (int u = 0; u < NTOPq; u++) {
        int s = g_mtop[bh * NTOPq + u];
        float otv = (lane < 16) ? g_ot[((size_t)bh * NTOPq + u) * DKq + lane] : 0.f;
        float corr = 0.f;
#pragma unroll
        for (int i = 0; i < 16; i++)
            corr += (__shfl_sync(0xffffffffu, otv, i) - mi[i]) * wh[i];
        atomicAdd(&out[((size_t)b * Sq + s) * DMq + j], corr);
    }
}

// -------------------------------------------------------------------------------
extern "C" void kernel_launch(void* const* d_in, const int* in_sizes, int n_in,
                              void* d_out, int out_size) {
    const float* query = (const float*)d_in[0];
    const float* key   = (const float*)d_in[1];
    const float* value = (const float*)d_in[2];
    const float* ckw   = (const float*)d_in[3];
    const float* ckb   = (const float*)d_in[4];
    const float* cvw   = (const float*)d_in[5];
    const float* cvb   = (const float*)d_in[6];
    const float* lw    = (const float*)d_in[7];
    const float* lb    = (const float*)d_in[8];
    const int*   isamp = (const int*)d_in[9];
    float* out = (float*)d_out;

    static int attr_set = 0;
    static void* mean_ptr = nullptr;
    if (!attr_set) {
        cudaFuncSetAttribute(conv_mma_kernel, cudaFuncAttributeMaxDynamicSharedMemorySize,
                             CONV_SMEM3);
        cudaFuncSetAttribute(select_attend_kernel, cudaFuncAttributeMaxDynamicSharedMemorySize,
                             FK_SMEM);
        cudaGetSymbolAddress(&mean_ptr, g_mean);
        attr_set = 1;
    }

    trig_kernel<<<(Sq * 64 + 255) / 256, 256>>>();
    rotary_kernel<<<(Bq * Sq * 32 + 255) / 256, 256>>>(query, key);
    wprep_kernel<<<(2 * 2 * 56 * ATILE_U4 + 255) / 256, 256>>>(ckw, cvw);
    cudaMemsetAsync(mean_ptr, 0, (size_t)Bq * DMq * sizeof(float));

    dim3 cgrid(2, Bq, 2);
    conv_mma_kernel<<<cgrid, 256, CONV_SMEM3>>>(value, ckb, cvb);

    select_attend_kernel<<<Bq * Hq, 256, FK_SMEM>>>(isamp);

    base_kernel<<<Bq, 256>>>(lw, lb, out);
    scatter_kernel<<<Bq * Hq, 128>>>(lw, out);
}